// round 1
// baseline (speedup 1.0000x reference)
#include <cuda_runtime.h>
#include <cuda_fp16.h>
#include <mma.h>

using namespace nvcuda;

// ---------------- problem constants ----------------
namespace {
constexpr int Bb = 4, Tt = 1024, Cc = 960, Hh = 15, Nn = 64;
constexpr int Mm = Bb * Tt;                    // 4096 tokens
constexpr float LN_EPS_F = 0.00064f;
constexpr float EXP_NEG_HALF = 0.6065306597126334f;

constexpr size_t MC  = (size_t)Mm * Cc;        // 3,932,160
constexpr size_t SZ_H_MC = MC * 2;             // fp16 token matrix bytes
constexpr size_t SZ_F_MC = MC * 4;             // fp32 token matrix bytes

// ---- scratch layout (all sizes multiples of 256B) ----
constexpr size_t O_XR   = 0;
constexpr size_t O_XW   = O_XR + SZ_H_MC;
constexpr size_t O_XK   = O_XW + SZ_H_MC;
constexpr size_t O_XV   = O_XK + SZ_H_MC;
constexpr size_t O_XA   = O_XV + SZ_H_MC;
constexpr size_t O_XG   = O_XA + SZ_H_MC;
constexpr size_t O_WR16 = O_XG + SZ_H_MC;
constexpr size_t O_WK16 = O_WR16 + (size_t)Cc * Cc * 2;
constexpr size_t O_WV16 = O_WK16 + (size_t)Cc * Cc * 2;
constexpr size_t O_WO16 = O_WV16 + (size_t)Cc * Cc * 2;
constexpr size_t O_W116 = O_WO16 + (size_t)Cc * Cc * 2;
constexpr size_t O_A116 = O_W116 + (size_t)Cc * 64 * 2;
constexpr size_t O_V116 = O_A116 + (size_t)Cc * 64 * 2;
constexpr size_t O_G116 = O_V116 + (size_t)Cc * 32 * 2;
constexpr size_t O_W216 = O_G116 + (size_t)Cc * 128 * 2;
constexpr size_t O_A216 = O_W216 + (size_t)64 * Cc * 2;
constexpr size_t O_V216 = O_A216 + (size_t)64 * Cc * 2;
constexpr size_t O_G216 = O_V216 + (size_t)32 * Cc * 2;
constexpr size_t O_HW   = O_G216 + (size_t)128 * Cc * 2;
constexpr size_t O_HA   = O_HW + (size_t)Mm * 64 * 2;
constexpr size_t O_HV   = O_HA + (size_t)Mm * 64 * 2;
constexpr size_t O_HG   = O_HV + (size_t)Mm * 32 * 2;
constexpr size_t O_R    = O_HG + (size_t)Mm * 128 * 2;
constexpr size_t O_K    = O_R + SZ_F_MC;
constexpr size_t O_V    = O_K + SZ_F_MC;
constexpr size_t O_WRAW = O_V + SZ_F_MC;
constexpr size_t O_ARAW = O_WRAW + SZ_F_MC;
constexpr size_t O_VRAW = O_ARAW + SZ_F_MC;
constexpr size_t O_GG   = O_VRAW + SZ_F_MC;
constexpr size_t O_SR   = O_GG + SZ_F_MC;
constexpr size_t O_SW   = O_SR + SZ_F_MC;
constexpr size_t O_SK   = O_SW + SZ_F_MC;
constexpr size_t O_SV   = O_SK + SZ_F_MC;
constexpr size_t O_SA   = O_SV + SZ_F_MC;
constexpr size_t O_SB   = O_SA + SZ_F_MC;
constexpr size_t O_COEF = O_SB + SZ_F_MC;
constexpr size_t O_WKV  = O_COEF + (size_t)Bb * Hh * Tt * 4;
constexpr size_t O_XO   = O_WKV + SZ_F_MC;
constexpr size_t SCRATCH_TOTAL = O_XO + SZ_H_MC;
} // namespace

__device__ __align__(256) unsigned char g_scratch[SCRATCH_TOTAL];

// ---------------- small helpers ----------------
__device__ __forceinline__ float sigmoidf_(float x) { return 1.f / (1.f + expf(-x)); }
__device__ __forceinline__ float getc(const float4& v, int j) {
    return j == 0 ? v.x : j == 1 ? v.y : j == 2 ? v.z : v.w;
}

// ---------------- fp32 -> fp16 convert ----------------
__global__ void k_convert(const float* __restrict__ src, __half* __restrict__ dst, int n) {
    int i = blockIdx.x * blockDim.x + threadIdx.x;
    if (i < n) dst[i] = __float2half(src[i]);
}

// ---------------- token shift + mix (6 outputs, fp16) ----------------
__global__ void k_mix(const float* __restrict__ x,
                      const float* __restrict__ mr, const float* __restrict__ mw,
                      const float* __restrict__ mk, const float* __restrict__ mv,
                      const float* __restrict__ ma, const float* __restrict__ mg,
                      __half* __restrict__ xr, __half* __restrict__ xw,
                      __half* __restrict__ xk, __half* __restrict__ xv,
                      __half* __restrict__ xa, __half* __restrict__ xg) {
    int i = blockIdx.x * blockDim.x + threadIdx.x;
    if (i >= Mm * (Cc / 4)) return;
    int m = i / (Cc / 4);
    int c = (i % (Cc / 4)) * 4;
    int t = m & (Tt - 1);
    float4 xc = *(const float4*)(x + (size_t)m * Cc + c);
    float4 xp = make_float4(0.f, 0.f, 0.f, 0.f);
    if (t > 0) xp = *(const float4*)(x + (size_t)(m - 1) * Cc + c);
    float4 dx = make_float4(xp.x - xc.x, xp.y - xc.y, xp.z - xc.z, xp.w - xc.w);

    const float* mixes[6] = {mr, mw, mk, mv, ma, mg};
    __half* outs[6] = {xr, xw, xk, xv, xa, xg};
#pragma unroll
    for (int q = 0; q < 6; q++) {
        float4 mmv = *(const float4*)(mixes[q] + c);
        __half2 h0 = __floats2half2_rn(xc.x + dx.x * mmv.x, xc.y + dx.y * mmv.y);
        __half2 h1 = __floats2half2_rn(xc.z + dx.z * mmv.z, xc.w + dx.w * mmv.w);
        *(__half2*)(outs[q] + (size_t)m * Cc + c)     = h0;
        *(__half2*)(outs[q] + (size_t)m * Cc + c + 2) = h1;
    }
}

// ---------------- wmma GEMM: C[M,N] = A[M,K] @ B[K,N] ----------------
// A,B fp16 row-major; EPI: 0 = fp32 store, 1 = tanh->fp16, 2 = sigmoid->fp16, 3 = fp16 store
template <int EPI>
__global__ void __launch_bounds__(256) k_gemm(const __half* __restrict__ A,
                                              const __half* __restrict__ Bm,
                                              void* __restrict__ Cout,
                                              int Md, int Nd, int Kd) {
    constexpr int BM = 128, BN = 64, BK = 32;
    constexpr int LDA = 40, LDB = 72, LDC = 68;
    constexpr int SMEM_AB = (BM * LDA + BK * LDB) * 2;
    constexpr int SMEM_C  = BM * LDC * 4;
    constexpr int SMEM_SZ = SMEM_C > SMEM_AB ? SMEM_C : SMEM_AB;
    __shared__ __align__(16) unsigned char smem_raw[SMEM_SZ];
    __half* sA = (__half*)smem_raw;            // [BM][LDA]
    __half* sB = (__half*)smem_raw + BM * LDA; // [BK][LDB]
    float*  sC = (float*)smem_raw;             // [BM][LDC] (reused after K loop)

    int tid = threadIdx.x;
    int bm = blockIdx.y * BM;
    int bn = blockIdx.x * BN;
    int warp = tid >> 5;
    int wr = warp & 3;   // 4 warps along M (32 rows each)
    int wc = warp >> 2;  // 2 warps along N (32 cols each)

    wmma::fragment<wmma::accumulator, 16, 16, 16, float> acc[2][2];
#pragma unroll
    for (int i = 0; i < 2; i++)
#pragma unroll
        for (int j = 0; j < 2; j++) wmma::fill_fragment(acc[i][j], 0.f);

    for (int k0 = 0; k0 < Kd; k0 += BK) {
        // A tile: 128x32 halves = 512 uint4; 2 per thread
#pragma unroll
        for (int u = 0; u < 2; u++) {
            int li = tid + u * 256;
            int r = li >> 2;
            int cv = (li & 3) * 8;
            *(uint4*)(sA + r * LDA + cv) =
                *(const uint4*)(A + (size_t)(bm + r) * Kd + k0 + cv);
        }
        // B tile: 32x64 halves = 256 uint4; 1 per thread
        {
            int r = tid >> 3;
            int cv = (tid & 7) * 8;
            uint4 val = make_uint4(0u, 0u, 0u, 0u);
            if (bn + cv < Nd)
                val = *(const uint4*)(Bm + (size_t)(k0 + r) * Nd + bn + cv);
            *(uint4*)(sB + r * LDB + cv) = val;
        }
        __syncthreads();
#pragma unroll
        for (int ks = 0; ks < 2; ks++) {
            wmma::fragment<wmma::matrix_a, 16, 16, 16, __half, wmma::row_major> fa[2];
            wmma::fragment<wmma::matrix_b, 16, 16, 16, __half, wmma::row_major> fb[2];
            wmma::load_matrix_sync(fa[0], sA + (wr * 32 + 0) * LDA + ks * 16, LDA);
            wmma::load_matrix_sync(fa[1], sA + (wr * 32 + 16) * LDA + ks * 16, LDA);
            wmma::load_matrix_sync(fb[0], sB + (ks * 16) * LDB + wc * 32, LDB);
            wmma::load_matrix_sync(fb[1], sB + (ks * 16) * LDB + wc * 32 + 16, LDB);
            wmma::mma_sync(acc[0][0], fa[0], fb[0], acc[0][0]);
            wmma::mma_sync(acc[0][1], fa[0], fb[1], acc[0][1]);
            wmma::mma_sync(acc[1][0], fa[1], fb[0], acc[1][0]);
            wmma::mma_sync(acc[1][1], fa[1], fb[1], acc[1][1]);
        }
        __syncthreads();
    }

#pragma unroll
    for (int i = 0; i < 2; i++)
#pragma unroll
        for (int j = 0; j < 2; j++)
            wmma::store_matrix_sync(sC + (wr * 32 + i * 16) * LDC + wc * 32 + j * 16,
                                    acc[i][j], LDC, wmma::mem_row_major);
    __syncthreads();

    for (int idx = tid; idx < BM * BN; idx += 256) {
        int r = idx >> 6;
        int c = idx & 63;
        int gc = bn + c;
        if (gc < Nd) {
            float v = sC[r * LDC + c];
            size_t gi = (size_t)(bm + r) * Nd + gc;
            if (EPI == 0)      ((float*)Cout)[gi]  = v;
            else if (EPI == 1) ((__half*)Cout)[gi] = __float2half(tanhf(v));
            else if (EPI == 2) ((__half*)Cout)[gi] = __float2half(sigmoidf_(v));
            else               ((__half*)Cout)[gi] = __float2half(v);
        }
    }
}

// ---------------- per-token prepare: scan inputs + bonus coef ----------------
__global__ void k_prepare(const float* __restrict__ Rf, const float* __restrict__ Kf,
                          const float* __restrict__ Vf, const float* __restrict__ WRAW,
                          const float* __restrict__ ARAW, const float* __restrict__ VRAW,
                          const float* __restrict__ vfirst,
                          const float* __restrict__ w0, const float* __restrict__ a0,
                          const float* __restrict__ v0, const float* __restrict__ kkw,
                          const float* __restrict__ kaw, const float* __restrict__ rkw,
                          float* __restrict__ SR, float* __restrict__ SW,
                          float* __restrict__ SK, float* __restrict__ SV,
                          float* __restrict__ SA, float* __restrict__ SB_,
                          float* __restrict__ COEF) {
    int gw = (blockIdx.x * blockDim.x + threadIdx.x) >> 5;
    int lane = threadIdx.x & 31;
    if (gw >= Mm * Hh) return;
    int m = gw / Hh;
    int h = gw % Hh;
    int b = m >> 10;
    int t = m & (Tt - 1);
    int n = lane * 2;
    int c = h * Nn + n;
    size_t gbase = (size_t)m * Cc + c;

    float2 k2   = *(const float2*)(Kf + gbase);
    float2 kkwv = *(const float2*)(kkw + c);
    float kkx = k2.x * kkwv.x, kky = k2.y * kkwv.y;
    float ss = kkx * kkx + kky * kky;
#pragma unroll
    for (int o = 16; o; o >>= 1) ss += __shfl_xor_sync(0xffffffffu, ss, o);
    float inv = 1.f / fmaxf(sqrtf(ss), 1e-12f);

    float2 ar2 = *(const float2*)(ARAW + gbase);
    float2 a0v = *(const float2*)(a0 + c);
    float ax = sigmoidf_(a0v.x + ar2.x);
    float ay = sigmoidf_(a0v.y + ar2.y);

    float2 kav = *(const float2*)(kaw + c);
    float khx = k2.x * (1.f + (ax - 1.f) * kav.x);
    float khy = k2.y * (1.f + (ay - 1.f) * kav.y);

    float2 wr2 = *(const float2*)(WRAW + gbase);
    float2 w0v = *(const float2*)(w0 + c);
    float wx = EXP_NEG_HALF * sigmoidf_(w0v.x + wr2.x);
    float wy = EXP_NEG_HALF * sigmoidf_(w0v.y + wr2.y);

    float2 vr2 = *(const float2*)(VRAW + gbase);
    float2 v0v = *(const float2*)(v0 + c);
    float svx = sigmoidf_(v0v.x + vr2.x);
    float svy = sigmoidf_(v0v.y + vr2.y);
    float2 vv  = *(const float2*)(Vf + gbase);
    float2 vf2 = *(const float2*)(vfirst + gbase);
    float vhx = vv.x + (vf2.x - vv.x) * svx;
    float vhy = vv.y + (vf2.y - vv.y) * svy;

    float2 r2  = *(const float2*)(Rf + gbase);
    float2 rkv = *(const float2*)(rkw + c);
    float cf = r2.x * khx * rkv.x + r2.y * khy * rkv.y;
#pragma unroll
    for (int o = 16; o; o >>= 1) cf += __shfl_xor_sync(0xffffffffu, cf, o);

    int bh = b * Hh + h;
    size_t sbase = ((size_t)bh * Tt + t) * Nn + n;
    *(float2*)(SR + sbase)  = r2;
    *(float2*)(SW + sbase)  = make_float2(wx, wy);
    *(float2*)(SK + sbase)  = make_float2(khx, khy);
    *(float2*)(SV + sbase)  = make_float2(vhx, vhy);
    *(float2*)(SA + sbase)  = make_float2(-kkx * inv, -kky * inv);
    *(float2*)(SB_ + sbase) = make_float2(kkx * inv * ax, kky * inv * ay);
    if (lane == 0) COEF[(size_t)bh * Tt + t] = cf;
}

// ---------------- sequential scan over T ----------------
// grid = B*H*(N/8) = 480 blocks; block = 64 threads (8 rows x 8 col-groups)
__global__ void __launch_bounds__(64) k_scan(const float* __restrict__ SR,
                                             const float* __restrict__ SW,
                                             const float* __restrict__ SK,
                                             const float* __restrict__ SV,
                                             const float* __restrict__ SA,
                                             const float* __restrict__ SB_,
                                             float* __restrict__ WKV) {
    int blk = blockIdx.x;
    int bh = blk >> 3;
    int q = blk & 7;
    int tid = threadIdx.x;
    int rowl = tid >> 3;
    int cg = tid & 7;
    int row = q * 8 + rowl;
    size_t base = (size_t)bh * Tt * Nn;
    int co = cg * 8;

    float st[8];
#pragma unroll
    for (int j = 0; j < 8; j++) st[j] = 0.f;

    // vector order: 0=W 1=A 2=B 3=K 4=R
    float4 cur[5][2], nxt[5][2];
    float cv, nv;
    {
        size_t o = base + co;
        cur[0][0] = __ldg((const float4*)(SW + o));  cur[0][1] = __ldg((const float4*)(SW + o + 4));
        cur[1][0] = __ldg((const float4*)(SA + o));  cur[1][1] = __ldg((const float4*)(SA + o + 4));
        cur[2][0] = __ldg((const float4*)(SB_ + o)); cur[2][1] = __ldg((const float4*)(SB_ + o + 4));
        cur[3][0] = __ldg((const float4*)(SK + o));  cur[3][1] = __ldg((const float4*)(SK + o + 4));
        cur[4][0] = __ldg((const float4*)(SR + o));  cur[4][1] = __ldg((const float4*)(SR + o + 4));
        cv = __ldg(SV + base + row);
    }

    for (int t = 0; t < Tt; t++) {
        int tn = (t + 1 < Tt) ? t + 1 : t;
        size_t on = base + (size_t)tn * Nn + co;
        nxt[0][0] = __ldg((const float4*)(SW + on));  nxt[0][1] = __ldg((const float4*)(SW + on + 4));
        nxt[1][0] = __ldg((const float4*)(SA + on));  nxt[1][1] = __ldg((const float4*)(SA + on + 4));
        nxt[2][0] = __ldg((const float4*)(SB_ + on)); nxt[2][1] = __ldg((const float4*)(SB_ + on + 4));
        nxt[3][0] = __ldg((const float4*)(SK + on));  nxt[3][1] = __ldg((const float4*)(SK + on + 4));
        nxt[4][0] = __ldg((const float4*)(SR + on));  nxt[4][1] = __ldg((const float4*)(SR + on + 4));
        nv = __ldg(SV + base + (size_t)tn * Nn + row);

        // sa_i = sum_j s[i][j] * a[j]  (partial over 8 cols, reduce across 8 lanes)
        float sa = 0.f;
#pragma unroll
        for (int j = 0; j < 8; j++) sa = fmaf(st[j], getc(cur[1][j >> 2], j & 3), sa);
        sa += __shfl_xor_sync(0xffffffffu, sa, 1);
        sa += __shfl_xor_sync(0xffffffffu, sa, 2);
        sa += __shfl_xor_sync(0xffffffffu, sa, 4);

        float outp = 0.f;
#pragma unroll
        for (int j = 0; j < 8; j++) {
            float wj = getc(cur[0][j >> 2], j & 3);
            float bj = getc(cur[2][j >> 2], j & 3);
            float kj = getc(cur[3][j >> 2], j & 3);
            float rj = getc(cur[4][j >> 2], j & 3);
            float s = fmaf(st[j], wj, fmaf(sa, bj, cv * kj));
            st[j] = s;
            outp = fmaf(s, rj, outp);
        }
        outp += __shfl_xor_sync(0xffffffffu, outp, 1);
        outp += __shfl_xor_sync(0xffffffffu, outp, 2);
        outp += __shfl_xor_sync(0xffffffffu, outp, 4);
        if (cg == 0) WKV[base + (size_t)t * Nn + row] = outp;

#pragma unroll
        for (int v = 0; v < 5; v++) { cur[v][0] = nxt[v][0]; cur[v][1] = nxt[v][1]; }
        cv = nv;
    }
}

// ---------------- groupnorm + bonus + gate -> fp16 A for final GEMM ----------------
__global__ void k_gn(const float* __restrict__ WKV, const float* __restrict__ SV,
                     const float* __restrict__ COEF, const float* __restrict__ GG,
                     const float* __restrict__ lng, const float* __restrict__ lnb,
                     __half* __restrict__ XO) {
    int gw = (blockIdx.x * blockDim.x + threadIdx.x) >> 5;
    int lane = threadIdx.x & 31;
    if (gw >= Mm * Hh) return;
    int m = gw / Hh;
    int h = gw % Hh;
    int b = m >> 10;
    int t = m & (Tt - 1);
    int bh = b * Hh + h;
    int n = lane * 2;
    int c = h * Nn + n;
    size_t sbase = ((size_t)bh * Tt + t) * Nn + n;

    float2 x2 = *(const float2*)(WKV + sbase);
    float s1 = x2.x + x2.y;
    float s2 = x2.x * x2.x + x2.y * x2.y;
#pragma unroll
    for (int o = 16; o; o >>= 1) {
        s1 += __shfl_xor_sync(0xffffffffu, s1, o);
        s2 += __shfl_xor_sync(0xffffffffu, s2, o);
    }
    float mu = s1 * (1.f / 64.f);
    float var = s2 * (1.f / 64.f) - mu * mu;
    float inv = rsqrtf(fmaxf(var, 0.f) + LN_EPS_F);

    float2 g2v = *(const float2*)(lng + c);
    float2 b2v = *(const float2*)(lnb + c);
    float xn0 = (x2.x - mu) * inv * g2v.x + b2v.x;
    float xn1 = (x2.y - mu) * inv * g2v.y + b2v.y;

    float cf = COEF[(size_t)bh * Tt + t];
    float2 vh2 = *(const float2*)(SV + sbase);
    float xo0 = xn0 + cf * vh2.x;
    float xo1 = xn1 + cf * vh2.y;

    float2 gg2 = *(const float2*)(GG + (size_t)m * Cc + c);
    *(__half2*)(XO + (size_t)m * Cc + c) = __floats2half2_rn(xo0 * gg2.x, xo1 * gg2.y);
}

// ---------------- host launcher ----------------
static inline int cdiv_(int a, int b) { return (a + b - 1) / b; }

extern "C" void kernel_launch(void* const* d_in, const int* in_sizes, int n_in,
                              void* d_out, int out_size) {
    (void)in_sizes; (void)n_in; (void)out_size;
    const float* x       = (const float*)d_in[0];
    const float* v_first = (const float*)d_in[1];
    const float* x_r  = (const float*)d_in[2];
    const float* x_w  = (const float*)d_in[3];
    const float* x_k  = (const float*)d_in[4];
    const float* x_v  = (const float*)d_in[5];
    const float* x_a  = (const float*)d_in[6];
    const float* x_g  = (const float*)d_in[7];
    const float* w0   = (const float*)d_in[8];
    const float* w1   = (const float*)d_in[9];
    const float* w2   = (const float*)d_in[10];
    const float* a0   = (const float*)d_in[11];
    const float* a1   = (const float*)d_in[12];
    const float* a2   = (const float*)d_in[13];
    const float* v0   = (const float*)d_in[14];
    const float* v1   = (const float*)d_in[15];
    const float* v2   = (const float*)d_in[16];
    const float* g1   = (const float*)d_in[17];
    const float* g2   = (const float*)d_in[18];
    const float* k_k  = (const float*)d_in[19];
    const float* k_a  = (const float*)d_in[20];
    const float* r_k  = (const float*)d_in[21];
    const float* Wr   = (const float*)d_in[22];
    const float* Wk   = (const float*)d_in[23];
    const float* Wv   = (const float*)d_in[24];
    const float* Wo   = (const float*)d_in[25];
    const float* ln_g = (const float*)d_in[26];
    const float* ln_b = (const float*)d_in[27];

    unsigned char* S = nullptr;
    cudaGetSymbolAddress((void**)&S, g_scratch);

    __half* XR = (__half*)(S + O_XR);   __half* XW = (__half*)(S + O_XW);
    __half* XK = (__half*)(S + O_XK);   __half* XV = (__half*)(S + O_XV);
    __half* XA = (__half*)(S + O_XA);   __half* XG = (__half*)(S + O_XG);
    __half* WR16 = (__half*)(S + O_WR16); __half* WK16 = (__half*)(S + O_WK16);
    __half* WV16 = (__half*)(S + O_WV16); __half* WO16 = (__half*)(S + O_WO16);
    __half* W116 = (__half*)(S + O_W116); __half* A116 = (__half*)(S + O_A116);
    __half* V116 = (__half*)(S + O_V116); __half* G116 = (__half*)(S + O_G116);
    __half* W216 = (__half*)(S + O_W216); __half* A216 = (__half*)(S + O_A216);
    __half* V216 = (__half*)(S + O_V216); __half* G216 = (__half*)(S + O_G216);
    __half* HW = (__half*)(S + O_HW); __half* HA = (__half*)(S + O_HA);
    __half* HV = (__half*)(S + O_HV); __half* HG = (__half*)(S + O_HG);
    float* Rf   = (float*)(S + O_R);    float* Kf   = (float*)(S + O_K);
    float* Vf   = (float*)(S + O_V);
    float* WRAW = (float*)(S + O_WRAW); float* ARAW = (float*)(S + O_ARAW);
    float* VRAW = (float*)(S + O_VRAW); float* GGp  = (float*)(S + O_GG);
    float* SR = (float*)(S + O_SR); float* SW = (float*)(S + O_SW);
    float* SK = (float*)(S + O_SK); float* SVp = (float*)(S + O_SV);
    float* SA = (float*)(S + O_SA); float* SBp = (float*)(S + O_SB);
    float* COEF = (float*)(S + O_COEF); float* WKVp = (float*)(S + O_WKV);
    __half* XO = (__half*)(S + O_XO);

    auto conv = [](const float* src, __half* dst, int n) {
        k_convert<<<cdiv_(n, 256), 256>>>(src, dst, n);
    };
    conv(Wr, WR16, Cc * Cc); conv(Wk, WK16, Cc * Cc);
    conv(Wv, WV16, Cc * Cc); conv(Wo, WO16, Cc * Cc);
    conv(w1, W116, Cc * 64); conv(a1, A116, Cc * 64);
    conv(v1, V116, Cc * 32); conv(g1, G116, Cc * 128);
    conv(w2, W216, 64 * Cc); conv(a2, A216, 64 * Cc);
    conv(v2, V216, 32 * Cc); conv(g2, G216, 128 * Cc);

    k_mix<<<cdiv_(Mm * (Cc / 4), 256), 256>>>(x, x_r, x_w, x_k, x_v, x_a, x_g,
                                              XR, XW, XK, XV, XA, XG);

    dim3 gBig(cdiv_(Cc, 64), Mm / 128);
    k_gemm<0><<<gBig, 256>>>(XR, WR16, Rf, Mm, Cc, Cc);
    k_gemm<0><<<gBig, 256>>>(XK, WK16, Kf, Mm, Cc, Cc);
    k_gemm<0><<<gBig, 256>>>(XV, WV16, Vf, Mm, Cc, Cc);

    dim3 g64(1, Mm / 128), g128n(cdiv_(128, 64), Mm / 128);
    k_gemm<1><<<g64, 256>>>(XW, W116, HW, Mm, 64, Cc);   // tanh
    k_gemm<3><<<g64, 256>>>(XA, A116, HA, Mm, 64, Cc);
    k_gemm<3><<<g64, 256>>>(XV, V116, HV, Mm, 32, Cc);
    k_gemm<2><<<g128n, 256>>>(XG, G116, HG, Mm, 128, Cc); // sigmoid

    k_gemm<0><<<gBig, 256>>>(HW, W216, WRAW, Mm, Cc, 64);
    k_gemm<0><<<gBig, 256>>>(HA, A216, ARAW, Mm, Cc, 64);
    k_gemm<0><<<gBig, 256>>>(HV, V216, VRAW, Mm, Cc, 32);
    k_gemm<0><<<gBig, 256>>>(HG, G216, GGp, Mm, Cc, 128);

    k_prepare<<<Mm * Hh / 8, 256>>>(Rf, Kf, Vf, WRAW, ARAW, VRAW, v_first,
                                    w0, a0, v0, k_k, k_a, r_k,
                                    SR, SW, SK, SVp, SA, SBp, COEF);

    k_scan<<<Bb * Hh * (Nn / 8), 64>>>(SR, SW, SK, SVp, SA, SBp, WKVp);

    k_gn<<<Mm * Hh / 8, 256>>>(WKVp, SVp, COEF, GGp, ln_g, ln_b, XO);

    k_gemm<0><<<gBig, 256>>>(XO, WO16, (float*)d_out, Mm, Cc, Cc);
}

// round 3
// speedup vs baseline: 1.0918x; 1.0918x over previous
#include <cuda_runtime.h>
#include <cuda_fp16.h>
#include <mma.h>
#include <cstdint>

using namespace nvcuda;

// ---------------- problem constants ----------------
namespace {
constexpr int Bb = 4, Tt = 1024, Cc = 960, Hh = 15, Nn = 64;
constexpr int Mm = Bb * Tt;                    // 4096 tokens
constexpr float LN_EPS_F = 0.00064f;
constexpr float EXP_NEG_HALF = 0.6065306597126334f;

constexpr size_t MC  = (size_t)Mm * Cc;
constexpr size_t SZ_H_MC = MC * 2;
constexpr size_t SZ_F_MC = MC * 4;

constexpr size_t O_XR   = 0;
constexpr size_t O_XW   = O_XR + SZ_H_MC;
constexpr size_t O_XK   = O_XW + SZ_H_MC;
constexpr size_t O_XV   = O_XK + SZ_H_MC;
constexpr size_t O_XA   = O_XV + SZ_H_MC;
constexpr size_t O_XG   = O_XA + SZ_H_MC;
constexpr size_t O_WR16 = O_XG + SZ_H_MC;
constexpr size_t O_WK16 = O_WR16 + (size_t)Cc * Cc * 2;
constexpr size_t O_WV16 = O_WK16 + (size_t)Cc * Cc * 2;
constexpr size_t O_WO16 = O_WV16 + (size_t)Cc * Cc * 2;
constexpr size_t O_W116 = O_WO16 + (size_t)Cc * Cc * 2;
constexpr size_t O_A116 = O_W116 + (size_t)Cc * 64 * 2;
constexpr size_t O_V116 = O_A116 + (size_t)Cc * 64 * 2;
constexpr size_t O_G116 = O_V116 + (size_t)Cc * 32 * 2;
constexpr size_t O_W216 = O_G116 + (size_t)Cc * 128 * 2;
constexpr size_t O_A216 = O_W216 + (size_t)64 * Cc * 2;
constexpr size_t O_V216 = O_A216 + (size_t)64 * Cc * 2;
constexpr size_t O_G216 = O_V216 + (size_t)32 * Cc * 2;
constexpr size_t O_HW   = O_G216 + (size_t)128 * Cc * 2;
constexpr size_t O_HA   = O_HW + (size_t)Mm * 64 * 2;
constexpr size_t O_HV   = O_HA + (size_t)Mm * 64 * 2;
constexpr size_t O_HG   = O_HV + (size_t)Mm * 32 * 2;
constexpr size_t O_R    = O_HG + (size_t)Mm * 128 * 2;
constexpr size_t O_K    = O_R + SZ_F_MC;
constexpr size_t O_V    = O_K + SZ_F_MC;
constexpr size_t O_WRAW = O_V + SZ_F_MC;
constexpr size_t O_ARAW = O_WRAW + SZ_F_MC;
constexpr size_t O_VRAW = O_ARAW + SZ_F_MC;
constexpr size_t O_GG   = O_VRAW + SZ_F_MC;
constexpr size_t O_SR   = O_GG + SZ_F_MC;
constexpr size_t O_SW   = O_SR + SZ_F_MC;
constexpr size_t O_SK   = O_SW + SZ_F_MC;
constexpr size_t O_SV   = O_SK + SZ_F_MC;
constexpr size_t O_SA   = O_SV + SZ_F_MC;
constexpr size_t O_SB   = O_SA + SZ_F_MC;
constexpr size_t O_COEF = O_SB + SZ_F_MC;
constexpr size_t O_WKV  = O_COEF + (size_t)Bb * Hh * Tt * 4;
constexpr size_t O_XO   = O_WKV + SZ_F_MC;
constexpr size_t SCRATCH_TOTAL = O_XO + SZ_H_MC;

// GEMM tile config
constexpr int BM = 128, BN = 64, BK = 32;
constexpr int LDA = 40, LDB = 72, LDC = 68, NSTAGE = 3;
constexpr int SMEM_AB = NSTAGE * (BM * LDA + BK * LDB) * 2;   // 44544
constexpr int SMEM_C  = BM * LDC * 4;                         // 34816
constexpr int SMEM_BYTES = SMEM_AB > SMEM_C ? SMEM_AB : SMEM_C;
} // namespace

__device__ __align__(256) unsigned char g_scratch[SCRATCH_TOTAL];

// ---------------- helpers ----------------
__device__ __forceinline__ float sigmoidf_(float x) { return 1.f / (1.f + expf(-x)); }
__device__ __forceinline__ float getc(const float4& v, int j) {
    return j == 0 ? v.x : j == 1 ? v.y : j == 2 ? v.z : v.w;
}
__device__ __forceinline__ void cp_async16(void* smem_dst, const void* gsrc) {
    unsigned int d = (unsigned int)__cvta_generic_to_shared(smem_dst);
    asm volatile("cp.async.cg.shared.global [%0], [%1], 16;" :: "r"(d), "l"(gsrc));
}
__device__ __forceinline__ void cp_async16p(void* smem_dst, const void* gsrc, bool pred) {
    unsigned int d = (unsigned int)__cvta_generic_to_shared(smem_dst);
    int b = pred ? 16 : 0;
    asm volatile("cp.async.cg.shared.global [%0], [%1], 16, %2;" :: "r"(d), "l"(gsrc), "r"(b));
}
#define CP_COMMIT() asm volatile("cp.async.commit_group;")
#define CP_WAIT2()  asm volatile("cp.async.wait_group 2;")

// ---------------- fused weight convert ----------------
__global__ void k_convert_all(const float* p0, const float* p1, const float* p2,
                              const float* p3, const float* p4, const float* p5,
                              const float* p6, const float* p7, const float* p8,
                              const float* p9, const float* p10, const float* p11) {
    const int sizes[12] = {Cc * Cc, Cc * Cc, Cc * Cc, Cc * Cc,
                           Cc * 64, Cc * 64, Cc * 32, Cc * 128,
                           64 * Cc, 64 * Cc, 32 * Cc, 128 * Cc};
    const size_t doff[12] = {O_WR16, O_WK16, O_WV16, O_WO16,
                             O_W116, O_A116, O_V116, O_G116,
                             O_W216, O_A216, O_V216, O_G216};
    const float* srcs[12] = {p0, p1, p2, p3, p4, p5, p6, p7, p8, p9, p10, p11};
    int z = blockIdx.y;
    int n = sizes[z];
    int i = (blockIdx.x * 256 + threadIdx.x) * 4;
    if (i >= n) return;
    const float* s = srcs[z];
    __half* d = (__half*)(g_scratch + doff[z]);
    float4 v = *(const float4*)(s + i);
    *(__half2*)(d + i)     = __floats2half2_rn(v.x, v.y);
    *(__half2*)(d + i + 2) = __floats2half2_rn(v.z, v.w);
}

// ---------------- token shift + mix ----------------
__global__ void k_mix(const float* __restrict__ x,
                      const float* __restrict__ mr, const float* __restrict__ mw,
                      const float* __restrict__ mk, const float* __restrict__ mv,
                      const float* __restrict__ ma, const float* __restrict__ mg) {
    int i = blockIdx.x * blockDim.x + threadIdx.x;
    if (i >= Mm * (Cc / 4)) return;
    int m = i / (Cc / 4);
    int c = (i % (Cc / 4)) * 4;
    int t = m & (Tt - 1);
    float4 xc = *(const float4*)(x + (size_t)m * Cc + c);
    float4 xp = make_float4(0.f, 0.f, 0.f, 0.f);
    if (t > 0) xp = *(const float4*)(x + (size_t)(m - 1) * Cc + c);
    float4 dx = make_float4(xp.x - xc.x, xp.y - xc.y, xp.z - xc.z, xp.w - xc.w);

    const float* mixes[6] = {mr, mw, mk, mv, ma, mg};
    const size_t offs[6] = {O_XR, O_XW, O_XK, O_XV, O_XA, O_XG};
#pragma unroll
    for (int q = 0; q < 6; q++) {
        float4 mmv = *(const float4*)(mixes[q] + c);
        __half* out = (__half*)(g_scratch + offs[q]);
        __half2 h0 = __floats2half2_rn(xc.x + dx.x * mmv.x, xc.y + dx.y * mmv.y);
        __half2 h1 = __floats2half2_rn(xc.z + dx.z * mmv.z, xc.w + dx.w * mmv.w);
        *(__half2*)(out + (size_t)m * Cc + c)     = h0;
        *(__half2*)(out + (size_t)m * Cc + c + 2) = h1;
    }
}

// ---------------- pipelined wmma GEMM core ----------------
// C[M,Nd] = A[M,Kd] @ B[Kd,Nd]; epi: 0 fp32, 1 tanh->fp16, 2 sigmoid->fp16, 3 fp16
__device__ __forceinline__ void gemm_tile(const __half* __restrict__ A,
                                          const __half* __restrict__ Bm,
                                          void* __restrict__ Cout,
                                          int Nd, int Kd, int epi,
                                          int bm, int bn,
                                          unsigned char* smem_raw) {
    __half* sA = (__half*)smem_raw;                        // [NSTAGE][BM*LDA]
    __half* sB = ((__half*)smem_raw) + NSTAGE * BM * LDA;  // [NSTAGE][BK*LDB]
    float*  sC = (float*)smem_raw;

    int tid = threadIdx.x;
    int warp = tid >> 5;
    int wr = warp & 3;
    int wc = warp >> 2;
    int KT = Kd / BK;

    auto load_stage = [&](int kt, int s) {
        const __half* Ag = A + (size_t)bm * Kd + kt * BK;
        __half* sAs = sA + s * BM * LDA;
        __half* sBs = sB + s * BK * LDB;
#pragma unroll
        for (int u = 0; u < 2; u++) {
            int id = tid + u * 256;
            int r = id >> 2;
            int c = (id & 3) * 8;
            cp_async16(sAs + r * LDA + c, Ag + (size_t)r * Kd + c);
        }
        {
            int r = tid >> 3;
            int c = (tid & 7) * 8;
            bool p = (bn + c) < Nd;
            const __half* Bg = Bm + (size_t)(kt * BK + r) * Nd + bn + c;
            cp_async16p(sBs + r * LDB + c, p ? Bg : (const __half*)Bm, p);
        }
    };

    wmma::fragment<wmma::accumulator, 16, 16, 16, float> acc[2][2];
#pragma unroll
    for (int i = 0; i < 2; i++)
#pragma unroll
        for (int j = 0; j < 2; j++) wmma::fill_fragment(acc[i][j], 0.f);

    // prologue: stages 0,1
    load_stage(0, 0);
    CP_COMMIT();
    if (KT > 1) load_stage(1, 1);
    CP_COMMIT();

    for (int kt = 0; kt < KT; kt++) {
        if (kt + 2 < KT) load_stage(kt + 2, (kt + 2) % NSTAGE);
        CP_COMMIT();
        CP_WAIT2();
        __syncthreads();
        int s = kt % NSTAGE;
        const __half* sAs = sA + s * BM * LDA;
        const __half* sBs = sB + s * BK * LDB;
#pragma unroll
        for (int ks = 0; ks < 2; ks++) {
            wmma::fragment<wmma::matrix_a, 16, 16, 16, __half, wmma::row_major> fa[2];
            wmma::fragment<wmma::matrix_b, 16, 16, 16, __half, wmma::row_major> fb[2];
            wmma::load_matrix_sync(fa[0], sAs + (wr * 32 + 0) * LDA + ks * 16, LDA);
            wmma::load_matrix_sync(fa[1], sAs + (wr * 32 + 16) * LDA + ks * 16, LDA);
            wmma::load_matrix_sync(fb[0], sBs + (ks * 16) * LDB + wc * 32, LDB);
            wmma::load_matrix_sync(fb[1], sBs + (ks * 16) * LDB + wc * 32 + 16, LDB);
            wmma::mma_sync(acc[0][0], fa[0], fb[0], acc[0][0]);
            wmma::mma_sync(acc[0][1], fa[0], fb[1], acc[0][1]);
            wmma::mma_sync(acc[1][0], fa[1], fb[0], acc[1][0]);
            wmma::mma_sync(acc[1][1], fa[1], fb[1], acc[1][1]);
        }
        __syncthreads();
    }

#pragma unroll
    for (int i = 0; i < 2; i++)
#pragma unroll
        for (int j = 0; j < 2; j++)
            wmma::store_matrix_sync(sC + (wr * 32 + i * 16) * LDC + wc * 32 + j * 16,
                                    acc[i][j], LDC, wmma::mem_row_major);
    __syncthreads();

    for (int idx = tid; idx < BM * BN; idx += 256) {
        int r = idx >> 6;
        int c = idx & 63;
        int gc = bn + c;
        if (gc >= Nd) continue;
        float v = sC[r * LDC + c];
        size_t gi = (size_t)(bm + r) * Nd + gc;
        if (epi == 0)      ((float*)Cout)[gi]  = v;
        else if (epi == 1) ((__half*)Cout)[gi] = __float2half(tanhf(v));
        else if (epi == 2) ((__half*)Cout)[gi] = __float2half(sigmoidf_(v));
        else               ((__half*)Cout)[gi] = __float2half(v);
    }
}

// ---------------- batched GEMM wrappers ----------------
__global__ void __launch_bounds__(256) k_gemm_rkv() {
    __shared__ __align__(16) unsigned char sm[SMEM_BYTES];
    int z = blockIdx.z;
    const size_t aoff[3] = {O_XR, O_XK, O_XV};
    const size_t boff[3] = {O_WR16, O_WK16, O_WV16};
    const size_t coff[3] = {O_R, O_K, O_V};
    gemm_tile((const __half*)(g_scratch + aoff[z]), (const __half*)(g_scratch + boff[z]),
              (void*)(g_scratch + coff[z]), Cc, Cc, 0,
              blockIdx.y * BM, blockIdx.x * BN, sm);
}

__global__ void __launch_bounds__(256) k_gemm_lora_up() {
    __shared__ __align__(16) unsigned char sm[SMEM_BYTES];
    int z = blockIdx.z;
    const size_t aoff[4] = {O_XW, O_XA, O_XV, O_XG};
    const size_t boff[4] = {O_W116, O_A116, O_V116, O_G116};
    const size_t coff[4] = {O_HW, O_HA, O_HV, O_HG};
    const int nd[4] = {64, 64, 32, 128};
    const int ep[4] = {1, 3, 3, 2};
    int bn = blockIdx.x * BN;
    if (bn >= nd[z]) return;
    gemm_tile((const __half*)(g_scratch + aoff[z]), (const __half*)(g_scratch + boff[z]),
              (void*)(g_scratch + coff[z]), nd[z], Cc, ep[z],
              blockIdx.y * BM, bn, sm);
}

__global__ void __launch_bounds__(256) k_gemm_lora_down() {
    __shared__ __align__(16) unsigned char sm[SMEM_BYTES];
    int z = blockIdx.z;
    const size_t aoff[4] = {O_HW, O_HA, O_HV, O_HG};
    const size_t boff[4] = {O_W216, O_A216, O_V216, O_G216};
    const size_t coff[4] = {O_WRAW, O_ARAW, O_VRAW, O_GG};
    const int kd[4] = {64, 64, 32, 128};
    gemm_tile((const __half*)(g_scratch + aoff[z]), (const __half*)(g_scratch + boff[z]),
              (void*)(g_scratch + coff[z]), Cc, kd[z], 0,
              blockIdx.y * BM, blockIdx.x * BN, sm);
}

__global__ void __launch_bounds__(256) k_gemm_out(float* __restrict__ out) {
    __shared__ __align__(16) unsigned char sm[SMEM_BYTES];
    gemm_tile((const __half*)(g_scratch + O_XO), (const __half*)(g_scratch + O_WO16),
              (void*)out, Cc, Cc, 0, blockIdx.y * BM, blockIdx.x * BN, sm);
}

// ---------------- per-token prepare ----------------
__global__ void k_prepare(const float* __restrict__ vfirst,
                          const float* __restrict__ w0, const float* __restrict__ a0,
                          const float* __restrict__ v0, const float* __restrict__ kkw,
                          const float* __restrict__ kaw, const float* __restrict__ rkw) {
    const float* Rf   = (const float*)(g_scratch + O_R);
    const float* Kf   = (const float*)(g_scratch + O_K);
    const float* Vf   = (const float*)(g_scratch + O_V);
    const float* WRAW = (const float*)(g_scratch + O_WRAW);
    const float* ARAW = (const float*)(g_scratch + O_ARAW);
    const float* VRAW = (const float*)(g_scratch + O_VRAW);
    float* SR  = (float*)(g_scratch + O_SR);
    float* SW  = (float*)(g_scratch + O_SW);
    float* SK  = (float*)(g_scratch + O_SK);
    float* SV  = (float*)(g_scratch + O_SV);
    float* SA  = (float*)(g_scratch + O_SA);
    float* SB_ = (float*)(g_scratch + O_SB);
    float* COEF = (float*)(g_scratch + O_COEF);

    int gw = (blockIdx.x * blockDim.x + threadIdx.x) >> 5;
    int lane = threadIdx.x & 31;
    if (gw >= Mm * Hh) return;
    int m = gw / Hh;
    int h = gw % Hh;
    int b = m >> 10;
    int t = m & (Tt - 1);
    int n = lane * 2;
    int c = h * Nn + n;
    size_t gbase = (size_t)m * Cc + c;

    float2 k2   = *(const float2*)(Kf + gbase);
    float2 kkwv = *(const float2*)(kkw + c);
    float kkx = k2.x * kkwv.x, kky = k2.y * kkwv.y;
    float ss = kkx * kkx + kky * kky;
#pragma unroll
    for (int o = 16; o; o >>= 1) ss += __shfl_xor_sync(0xffffffffu, ss, o);
    float inv = 1.f / fmaxf(sqrtf(ss), 1e-12f);

    float2 ar2 = *(const float2*)(ARAW + gbase);
    float2 a0v = *(const float2*)(a0 + c);
    float ax = sigmoidf_(a0v.x + ar2.x);
    float ay = sigmoidf_(a0v.y + ar2.y);

    float2 kav = *(const float2*)(kaw + c);
    float khx = k2.x * (1.f + (ax - 1.f) * kav.x);
    float khy = k2.y * (1.f + (ay - 1.f) * kav.y);

    float2 wr2 = *(const float2*)(WRAW + gbase);
    float2 w0v = *(const float2*)(w0 + c);
    float wx = EXP_NEG_HALF * sigmoidf_(w0v.x + wr2.x);
    float wy = EXP_NEG_HALF * sigmoidf_(w0v.y + wr2.y);

    float2 vr2 = *(const float2*)(VRAW + gbase);
    float2 v0v = *(const float2*)(v0 + c);
    float svx = sigmoidf_(v0v.x + vr2.x);
    float svy = sigmoidf_(v0v.y + vr2.y);
    float2 vv  = *(const float2*)(Vf + gbase);
    float2 vf2 = *(const float2*)(vfirst + gbase);
    float vhx = vv.x + (vf2.x - vv.x) * svx;
    float vhy = vv.y + (vf2.y - vv.y) * svy;

    float2 r2  = *(const float2*)(Rf + gbase);
    float2 rkv = *(const float2*)(rkw + c);
    float cf = r2.x * khx * rkv.x + r2.y * khy * rkv.y;
#pragma unroll
    for (int o = 16; o; o >>= 1) cf += __shfl_xor_sync(0xffffffffu, cf, o);

    int bh = b * Hh + h;
    size_t sbase = ((size_t)bh * Tt + t) * Nn + n;
    *(float2*)(SR + sbase)  = r2;
    *(float2*)(SW + sbase)  = make_float2(wx, wy);
    *(float2*)(SK + sbase)  = make_float2(khx, khy);
    *(float2*)(SV + sbase)  = make_float2(vhx, vhy);
    *(float2*)(SA + sbase)  = make_float2(-kkx * inv, -kky * inv);
    *(float2*)(SB_ + sbase) = make_float2(kkx * inv * ax, kky * inv * ay);
    if (lane == 0) COEF[(size_t)bh * Tt + t] = cf;
}

// ---------------- sequential scan over T ----------------
__global__ void __launch_bounds__(64) k_scan() {
    const float* SR  = (const float*)(g_scratch + O_SR);
    const float* SW  = (const float*)(g_scratch + O_SW);
    const float* SK  = (const float*)(g_scratch + O_SK);
    const float* SV  = (const float*)(g_scratch + O_SV);
    const float* SA  = (const float*)(g_scratch + O_SA);
    const float* SB_ = (const float*)(g_scratch + O_SB);
    float* WKV = (float*)(g_scratch + O_WKV);

    int blk = blockIdx.x;
    int bh = blk >> 3;
    int q = blk & 7;
    int tid = threadIdx.x;
    int rowl = tid >> 3;
    int cg = tid & 7;
    int row = q * 8 + rowl;
    size_t base = (size_t)bh * Tt * Nn;
    int co = cg * 8;

    float st[8];
#pragma unroll
    for (int j = 0; j < 8; j++) st[j] = 0.f;

    float4 cur[5][2], nxt[5][2];
    float cv, nv;
    {
        size_t o = base + co;
        cur[0][0] = __ldg((const float4*)(SW + o));  cur[0][1] = __ldg((const float4*)(SW + o + 4));
        cur[1][0] = __ldg((const float4*)(SA + o));  cur[1][1] = __ldg((const float4*)(SA + o + 4));
        cur[2][0] = __ldg((const float4*)(SB_ + o)); cur[2][1] = __ldg((const float4*)(SB_ + o + 4));
        cur[3][0] = __ldg((const float4*)(SK + o));  cur[3][1] = __ldg((const float4*)(SK + o + 4));
        cur[4][0] = __ldg((const float4*)(SR + o));  cur[4][1] = __ldg((const float4*)(SR + o + 4));
        cv = __ldg(SV + base + row);
    }

    for (int t = 0; t < Tt; t++) {
        int tn = (t + 1 < Tt) ? t + 1 : t;
        size_t on = base + (size_t)tn * Nn + co;
        nxt[0][0] = __ldg((const float4*)(SW + on));  nxt[0][1] = __ldg((const float4*)(SW + on + 4));
        nxt[1][0] = __ldg((const float4*)(SA + on));  nxt[1][1] = __ldg((const float4*)(SA + on + 4));
        nxt[2][0] = __ldg((const float4*)(SB_ + on)); nxt[2][1] = __ldg((const float4*)(SB_ + on + 4));
        nxt[3][0] = __ldg((const float4*)(SK + on));  nxt[3][1] = __ldg((const float4*)(SK + on + 4));
        nxt[4][0] = __ldg((const float4*)(SR + on));  nxt[4][1] = __ldg((const float4*)(SR + on + 4));
        nv = __ldg(SV + base + (size_t)tn * Nn + row);

        float sa = 0.f;
#pragma unroll
        for (int j = 0; j < 8; j++) sa = fmaf(st[j], getc(cur[1][j >> 2], j & 3), sa);
        sa += __shfl_xor_sync(0xffffffffu, sa, 1);
        sa += __shfl_xor_sync(0xffffffffu, sa, 2);
        sa += __shfl_xor_sync(0xffffffffu, sa, 4);

        float outp = 0.f;
#pragma unroll
        for (int j = 0; j < 8; j++) {
            float wj = getc(cur[0][j >> 2], j & 3);
            float bj = getc(cur[2][j >> 2], j & 3);
            float kj = getc(cur[3][j >> 2], j & 3);
            float rj = getc(cur[4][j >> 2], j & 3);
            float s = fmaf(st[j], wj, fmaf(sa, bj, cv * kj));
            st[j] = s;
            outp = fmaf(s, rj, outp);
        }
        outp += __shfl_xor_sync(0xffffffffu, outp, 1);
        outp += __shfl_xor_sync(0xffffffffu, outp, 2);
        outp += __shfl_xor_sync(0xffffffffu, outp, 4);
        if (cg == 0) WKV[base + (size_t)t * Nn + row] = outp;

#pragma unroll
        for (int v = 0; v < 5; v++) { cur[v][0] = nxt[v][0]; cur[v][1] = nxt[v][1]; }
        cv = nv;
    }
}

// ---------------- groupnorm + bonus + gate ----------------
__global__ void k_gn(const float* __restrict__ lng, const float* __restrict__ lnb) {
    const float* WKV  = (const float*)(g_scratch + O_WKV);
    const float* SV   = (const float*)(g_scratch + O_SV);
    const float* COEF = (const float*)(g_scratch + O_COEF);
    const float* GG   = (const float*)(g_scratch + O_GG);
    __half* XO = (__half*)(g_scratch + O_XO);

    int gw = (blockIdx.x * blockDim.x + threadIdx.x) >> 5;
    int lane = threadIdx.x & 31;
    if (gw >= Mm * Hh) return;
    int m = gw / Hh;
    int h = gw % Hh;
    int b = m >> 10;
    int t = m & (Tt - 1);
    int bh = b * Hh + h;
    int n = lane * 2;
    int c = h * Nn + n;
    size_t sbase = ((size_t)bh * Tt + t) * Nn + n;

    float2 x2 = *(const float2*)(WKV + sbase);
    float s1 = x2.x + x2.y;
    float s2 = x2.x * x2.x + x2.y * x2.y;
#pragma unroll
    for (int o = 16; o; o >>= 1) {
        s1 += __shfl_xor_sync(0xffffffffu, s1, o);
        s2 += __shfl_xor_sync(0xffffffffu, s2, o);
    }
    float mu = s1 * (1.f / 64.f);
    float var = s2 * (1.f / 64.f) - mu * mu;
    float inv = rsqrtf(fmaxf(var, 0.f) + LN_EPS_F);

    float2 g2v = *(const float2*)(lng + c);
    float2 b2v = *(const float2*)(lnb + c);
    float xn0 = (x2.x - mu) * inv * g2v.x + b2v.x;
    float xn1 = (x2.y - mu) * inv * g2v.y + b2v.y;

    float cf = COEF[(size_t)bh * Tt + t];
    float2 vh2 = *(const float2*)(SV + sbase);
    float xo0 = xn0 + cf * vh2.x;
    float xo1 = xn1 + cf * vh2.y;

    float2 gg2 = *(const float2*)(GG + (size_t)m * Cc + c);
    *(__half2*)(XO + (size_t)m * Cc + c) = __floats2half2_rn(xo0 * gg2.x, xo1 * gg2.y);
}

// ---------------- host launcher ----------------
static inline int cdiv_(int a, int b) { return (a + b - 1) / b; }

extern "C" void kernel_launch(void* const* d_in, const int* in_sizes, int n_in,
                              void* d_out, int out_size) {
    (void)in_sizes; (void)n_in; (void)out_size;
    const float* x       = (const float*)d_in[0];
    const float* v_first = (const float*)d_in[1];
    const float* x_r  = (const float*)d_in[2];
    const float* x_w  = (const float*)d_in[3];
    const float* x_k  = (const float*)d_in[4];
    const float* x_v  = (const float*)d_in[5];
    const float* x_a  = (const float*)d_in[6];
    const float* x_g  = (const float*)d_in[7];
    const float* w0   = (const float*)d_in[8];
    const float* w1   = (const float*)d_in[9];
    const float* a0   = (const float*)d_in[11];
    const float* a1   = (const float*)d_in[12];
    const float* v0   = (const float*)d_in[14];
    const float* v1   = (const float*)d_in[15];
    const float* g1   = (const float*)d_in[17];
    const float* k_k  = (const float*)d_in[19];
    const float* k_a  = (const float*)d_in[20];
    const float* r_k  = (const float*)d_in[21];
    const float* ln_g = (const float*)d_in[26];
    const float* ln_b = (const float*)d_in[27];

    {
        dim3 g(cdiv_(Cc * Cc / 4, 256), 12);
        k_convert_all<<<g, 256>>>((const float*)d_in[22], (const float*)d_in[23],
                                  (const float*)d_in[24], (const float*)d_in[25],
                                  w1, a1, v1, g1,
                                  (const float*)d_in[10], (const float*)d_in[13],
                                  (const float*)d_in[16], (const float*)d_in[18]);
    }

    k_mix<<<cdiv_(Mm * (Cc / 4), 256), 256>>>(x, x_r, x_w, x_k, x_v, x_a, x_g);

    {
        dim3 g(Cc / BN, Mm / BM, 3);
        k_gemm_rkv<<<g, 256>>>();
    }
    {
        dim3 g(2, Mm / BM, 4);     // covers N up to 128
        k_gemm_lora_up<<<g, 256>>>();
    }
    {
        dim3 g(Cc / BN, Mm / BM, 4);
        k_gemm_lora_down<<<g, 256>>>();
    }

    k_prepare<<<Mm * Hh / 8, 256>>>(v_first, w0, a0, v0, k_k, k_a, r_k);

    k_scan<<<Bb * Hh * (Nn / 8), 64>>>();

    k_gn<<<Mm * Hh / 8, 256>>>(ln_g, ln_b);

    {
        dim3 g(Cc / BN, Mm / BM);
        k_gemm_out<<<g, 256>>>((float*)d_out);
    }
}

// round 5
// speedup vs baseline: 1.1177x; 1.0237x over previous
#include <cuda_runtime.h>
#include <cuda_fp16.h>
#include <mma.h>
#include <cstdint>

using namespace nvcuda;

// ---------------- problem constants ----------------
namespace {
constexpr int Bb = 4, Tt = 1024, Cc = 960, Hh = 15, Nn = 64;
constexpr int Mm = Bb * Tt;                    // 4096 tokens
constexpr float LN_EPS_F = 0.00064f;
constexpr float EXP_NEG_HALF = 0.6065306597126334f;

constexpr size_t MC  = (size_t)Mm * Cc;
constexpr size_t SZ_H_MC = MC * 2;
constexpr size_t SZ_F_MC = MC * 4;

constexpr size_t O_XR   = 0;
constexpr size_t O_XW   = O_XR + SZ_H_MC;
constexpr size_t O_XK   = O_XW + SZ_H_MC;
constexpr size_t O_XV   = O_XK + SZ_H_MC;
constexpr size_t O_XA   = O_XV + SZ_H_MC;
constexpr size_t O_XG   = O_XA + SZ_H_MC;
constexpr size_t O_WR16 = O_XG + SZ_H_MC;
constexpr size_t O_WK16 = O_WR16 + (size_t)Cc * Cc * 2;
constexpr size_t O_WV16 = O_WK16 + (size_t)Cc * Cc * 2;
constexpr size_t O_WO16 = O_WV16 + (size_t)Cc * Cc * 2;
constexpr size_t O_W116 = O_WO16 + (size_t)Cc * Cc * 2;
constexpr size_t O_A116 = O_W116 + (size_t)Cc * 64 * 2;
constexpr size_t O_V116 = O_A116 + (size_t)Cc * 64 * 2;
constexpr size_t O_G116 = O_V116 + (size_t)Cc * 32 * 2;
constexpr size_t O_W216 = O_G116 + (size_t)Cc * 128 * 2;
constexpr size_t O_A216 = O_W216 + (size_t)64 * Cc * 2;
constexpr size_t O_V216 = O_A216 + (size_t)64 * Cc * 2;
constexpr size_t O_G216 = O_V216 + (size_t)32 * Cc * 2;
constexpr size_t O_HW   = O_G216 + (size_t)128 * Cc * 2;
constexpr size_t O_HA   = O_HW + (size_t)Mm * 64 * 2;
constexpr size_t O_HV   = O_HA + (size_t)Mm * 64 * 2;
constexpr size_t O_HG   = O_HV + (size_t)Mm * 32 * 2;
constexpr size_t O_R    = O_HG + (size_t)Mm * 128 * 2;
constexpr size_t O_K    = O_R + SZ_F_MC;
constexpr size_t O_V    = O_K + SZ_F_MC;
constexpr size_t O_WRAW = O_V + SZ_F_MC;
constexpr size_t O_ARAW = O_WRAW + SZ_F_MC;
constexpr size_t O_VRAW = O_ARAW + SZ_F_MC;
constexpr size_t O_GG   = O_VRAW + SZ_F_MC;
constexpr size_t O_SR   = O_GG + SZ_F_MC;
constexpr size_t O_SW   = O_SR + SZ_F_MC;
constexpr size_t O_SK   = O_SW + SZ_F_MC;
constexpr size_t O_SV   = O_SK + SZ_F_MC;
constexpr size_t O_SA   = O_SV + SZ_F_MC;
constexpr size_t O_SB   = O_SA + SZ_F_MC;
constexpr size_t O_COEF = O_SB + SZ_F_MC;
constexpr size_t O_WKV  = O_COEF + (size_t)Bb * Hh * Tt * 4;
constexpr size_t O_XO   = O_WKV + SZ_F_MC;
constexpr size_t SCRATCH_TOTAL = O_XO + SZ_H_MC;

// old (fp16-epilogue) GEMM tile config
constexpr int BM = 128, BN = 64, BK = 32;
constexpr int LDA = 40, LDB = 72, LDC = 68, NSTAGE = 3;
constexpr int SMEM_AB = NSTAGE * (BM * LDA + BK * LDB) * 2;
constexpr int SMEM_C  = BM * LDC * 4;
constexpr int SMEM_BYTES = SMEM_AB > SMEM_C ? SMEM_AB : SMEM_C;

// new fast fp32-output GEMM config
constexpr int FBM = 128, FBN = 128, FBK = 32;
constexpr int FLDA = 40, FLDB = 136;
} // namespace

__device__ __align__(256) unsigned char g_scratch[SCRATCH_TOTAL];

// ---------------- helpers ----------------
__device__ __forceinline__ float sigmoidf_(float x) { return 1.f / (1.f + expf(-x)); }
__device__ __forceinline__ float getc(const float4& v, int j) {
    return j == 0 ? v.x : j == 1 ? v.y : j == 2 ? v.z : v.w;
}
__device__ __forceinline__ void cp_async16(void* smem_dst, const void* gsrc) {
    unsigned int d = (unsigned int)__cvta_generic_to_shared(smem_dst);
    asm volatile("cp.async.cg.shared.global [%0], [%1], 16;" :: "r"(d), "l"(gsrc));
}
__device__ __forceinline__ void cp_async16p(void* smem_dst, const void* gsrc, bool pred) {
    unsigned int d = (unsigned int)__cvta_generic_to_shared(smem_dst);
    int b = pred ? 16 : 0;
    asm volatile("cp.async.cg.shared.global [%0], [%1], 16, %2;" :: "r"(d), "l"(gsrc), "r"(b));
}
#define CP_COMMIT() asm volatile("cp.async.commit_group;")
#define CP_WAIT1()  asm volatile("cp.async.wait_group 1;")
#define CP_WAIT2()  asm volatile("cp.async.wait_group 2;")

// ---------------- fused weight convert ----------------
__global__ void k_convert_all(const float* p0, const float* p1, const float* p2,
                              const float* p3, const float* p4, const float* p5,
                              const float* p6, const float* p7, const float* p8,
                              const float* p9, const float* p10, const float* p11) {
    const int sizes[12] = {Cc * Cc, Cc * Cc, Cc * Cc, Cc * Cc,
                           Cc * 64, Cc * 64, Cc * 32, Cc * 128,
                           64 * Cc, 64 * Cc, 32 * Cc, 128 * Cc};
    const size_t doff[12] = {O_WR16, O_WK16, O_WV16, O_WO16,
                             O_W116, O_A116, O_V116, O_G116,
                             O_W216, O_A216, O_V216, O_G216};
    const float* srcs[12] = {p0, p1, p2, p3, p4, p5, p6, p7, p8, p9, p10, p11};
    int z = blockIdx.y;
    int n = sizes[z];
    int i = (blockIdx.x * 256 + threadIdx.x) * 4;
    if (i >= n) return;
    const float* s = srcs[z];
    __half* d = (__half*)(g_scratch + doff[z]);
    float4 v = *(const float4*)(s + i);
    *(__half2*)(d + i)     = __floats2half2_rn(v.x, v.y);
    *(__half2*)(d + i + 2) = __floats2half2_rn(v.z, v.w);
}

// ---------------- token shift + mix ----------------
__global__ void k_mix(const float* __restrict__ x,
                      const float* __restrict__ mr, const float* __restrict__ mw,
                      const float* __restrict__ mk, const float* __restrict__ mv,
                      const float* __restrict__ ma, const float* __restrict__ mg) {
    int i = blockIdx.x * blockDim.x + threadIdx.x;
    if (i >= Mm * (Cc / 4)) return;
    int m = i / (Cc / 4);
    int c = (i % (Cc / 4)) * 4;
    int t = m & (Tt - 1);
    float4 xc = *(const float4*)(x + (size_t)m * Cc + c);
    float4 xp = make_float4(0.f, 0.f, 0.f, 0.f);
    if (t > 0) xp = *(const float4*)(x + (size_t)(m - 1) * Cc + c);
    float4 dx = make_float4(xp.x - xc.x, xp.y - xc.y, xp.z - xc.z, xp.w - xc.w);

    const float* mixes[6] = {mr, mw, mk, mv, ma, mg};
    const size_t offs[6] = {O_XR, O_XW, O_XK, O_XV, O_XA, O_XG};
#pragma unroll
    for (int q = 0; q < 6; q++) {
        float4 mmv = *(const float4*)(mixes[q] + c);
        __half* out = (__half*)(g_scratch + offs[q]);
        __half2 h0 = __floats2half2_rn(xc.x + dx.x * mmv.x, xc.y + dx.y * mmv.y);
        __half2 h1 = __floats2half2_rn(xc.z + dx.z * mmv.z, xc.w + dx.w * mmv.w);
        *(__half2*)(out + (size_t)m * Cc + c)     = h0;
        *(__half2*)(out + (size_t)m * Cc + c + 2) = h1;
    }
}

// ---------------- NEW fast fp32-output GEMM: 64x32 warp tile, direct store ----------------
// C[M,Nd] (fp32) = A[M,Kd] @ B[Kd,Nd], 128x128 CTA tile, 8 warps (2M x 4N), 2-stage cp.async
__device__ __forceinline__ void gemm_fast(const __half* __restrict__ A,
                                          const __half* __restrict__ Bm,
                                          float* __restrict__ Cf,
                                          int Nd, int Kd,
                                          int bm, int bn,
                                          __half* sA, __half* sB) {
    int tid = threadIdx.x;
    int warp = tid >> 5;
    int wr = warp >> 2;     // 0..1  (M)
    int wc = warp & 3;      // 0..3  (N)
    int KT = Kd / FBK;

    auto load_stage = [&](int kt, int s) {
        const __half* Ag = A + (size_t)bm * Kd + kt * FBK;
        __half* sAs = sA + s * FBM * FLDA;
        __half* sBs = sB + s * FBK * FLDB;
        // A tile: 128x32 halves = 512 uint4, 2 per thread
#pragma unroll
        for (int u = 0; u < 2; u++) {
            int id = tid + u * 256;
            int r = id >> 2;
            int c = (id & 3) * 8;
            cp_async16(sAs + r * FLDA + c, Ag + (size_t)r * Kd + c);
        }
        // B tile: 32x128 halves = 512 uint4, 2 per thread
#pragma unroll
        for (int u = 0; u < 2; u++) {
            int id = tid + u * 256;
            int r = id >> 4;
            int c = (id & 15) * 8;
            bool p = (bn + c) < Nd;
            const __half* Bg = Bm + (size_t)(kt * FBK + r) * Nd + bn + c;
            cp_async16p(sBs + r * FLDB + c, p ? Bg : (const __half*)Bm, p);
        }
    };

    wmma::fragment<wmma::accumulator, 16, 16, 16, float> acc[4][2];
#pragma unroll
    for (int i = 0; i < 4; i++)
#pragma unroll
        for (int j = 0; j < 2; j++) wmma::fill_fragment(acc[i][j], 0.f);

    load_stage(0, 0);
    CP_COMMIT();

    for (int kt = 0; kt < KT; kt++) {
        if (kt + 1 < KT) load_stage(kt + 1, (kt + 1) & 1);
        CP_COMMIT();
        CP_WAIT1();
        __syncthreads();
        const __half* sAs = sA + (kt & 1) * FBM * FLDA;
        const __half* sBs = sB + (kt & 1) * FBK * FLDB;
#pragma unroll
        for (int ks = 0; ks < 2; ks++) {
            wmma::fragment<wmma::matrix_b, 16, 16, 16, __half, wmma::row_major> fb[2];
            wmma::load_matrix_sync(fb[0], sBs + (ks * 16) * FLDB + wc * 32, FLDB);
            wmma::load_matrix_sync(fb[1], sBs + (ks * 16) * FLDB + wc * 32 + 16, FLDB);
#pragma unroll
            for (int i = 0; i < 4; i++) {
                wmma::fragment<wmma::matrix_a, 16, 16, 16, __half, wmma::row_major> fa;
                wmma::load_matrix_sync(fa, sAs + (wr * 64 + i * 16) * FLDA + ks * 16, FLDA);
                wmma::mma_sync(acc[i][0], fa, fb[0], acc[i][0]);
                wmma::mma_sync(acc[i][1], fa, fb[1], acc[i][1]);
            }
        }
        __syncthreads();
    }

    // direct global store (fp32), fragment-granular N guard (Nd % 16 == 0)
#pragma unroll
    for (int i = 0; i < 4; i++)
#pragma unroll
        for (int j = 0; j < 2; j++) {
            int gc = bn + wc * 32 + j * 16;
            if (gc < Nd)
                wmma::store_matrix_sync(Cf + (size_t)(bm + wr * 64 + i * 16) * Nd + gc,
                                        acc[i][j], Nd, wmma::mem_row_major);
        }
}

__global__ void __launch_bounds__(256, 2) k2_gemm_rkv() {
    __shared__ __align__(16) __half sA[2 * FBM * FLDA];
    __shared__ __align__(16) __half sB[2 * FBK * FLDB];
    int z = blockIdx.z;
    const size_t aoff[3] = {O_XR, O_XK, O_XV};
    const size_t boff[3] = {O_WR16, O_WK16, O_WV16};
    const size_t coff[3] = {O_R, O_K, O_V};
    gemm_fast((const __half*)(g_scratch + aoff[z]), (const __half*)(g_scratch + boff[z]),
              (float*)(g_scratch + coff[z]), Cc, Cc,
              blockIdx.y * FBM, blockIdx.x * FBN, sA, sB);
}

__global__ void __launch_bounds__(256, 2) k2_gemm_down() {
    __shared__ __align__(16) __half sA[2 * FBM * FLDA];
    __shared__ __align__(16) __half sB[2 * FBK * FLDB];
    int z = blockIdx.z;
    const size_t aoff[4] = {O_HW, O_HA, O_HV, O_HG};
    const size_t boff[4] = {O_W216, O_A216, O_V216, O_G216};
    const size_t coff[4] = {O_WRAW, O_ARAW, O_VRAW, O_GG};
    const int kd[4] = {64, 64, 32, 128};
    gemm_fast((const __half*)(g_scratch + aoff[z]), (const __half*)(g_scratch + boff[z]),
              (float*)(g_scratch + coff[z]), Cc, kd[z],
              blockIdx.y * FBM, blockIdx.x * FBN, sA, sB);
}

__global__ void __launch_bounds__(256, 2) k2_gemm_out(float* __restrict__ out) {
    __shared__ __align__(16) __half sA[2 * FBM * FLDA];
    __shared__ __align__(16) __half sB[2 * FBK * FLDB];
    gemm_fast((const __half*)(g_scratch + O_XO), (const __half*)(g_scratch + O_WO16),
              out, Cc, Cc, blockIdx.y * FBM, blockIdx.x * FBN, sA, sB);
}

// ---------------- old pipelined wmma GEMM (fp16 epilogues, lora_up only) ----------------
__device__ __forceinline__ void gemm_tile(const __half* __restrict__ A,
                                          const __half* __restrict__ Bm,
                                          void* __restrict__ Cout,
                                          int Nd, int Kd, int epi,
                                          int bm, int bn,
                                          unsigned char* smem_raw) {
    __half* sA = (__half*)smem_raw;
    __half* sB = ((__half*)smem_raw) + NSTAGE * BM * LDA;
    float*  sC = (float*)smem_raw;

    int tid = threadIdx.x;
    int warp = tid >> 5;
    int wr = warp & 3;
    int wc = warp >> 2;
    int KT = Kd / BK;

    auto load_stage = [&](int kt, int s) {
        const __half* Ag = A + (size_t)bm * Kd + kt * BK;
        __half* sAs = sA + s * BM * LDA;
        __half* sBs = sB + s * BK * LDB;
#pragma unroll
        for (int u = 0; u < 2; u++) {
            int id = tid + u * 256;
            int r = id >> 2;
            int c = (id & 3) * 8;
            cp_async16(sAs + r * LDA + c, Ag + (size_t)r * Kd + c);
        }
        {
            int r = tid >> 3;
            int c = (tid & 7) * 8;
            bool p = (bn + c) < Nd;
            const __half* Bg = Bm + (size_t)(kt * BK + r) * Nd + bn + c;
            cp_async16p(sBs + r * LDB + c, p ? Bg : (const __half*)Bm, p);
        }
    };

    wmma::fragment<wmma::accumulator, 16, 16, 16, float> acc[2][2];
#pragma unroll
    for (int i = 0; i < 2; i++)
#pragma unroll
        for (int j = 0; j < 2; j++) wmma::fill_fragment(acc[i][j], 0.f);

    load_stage(0, 0);
    CP_COMMIT();
    if (KT > 1) load_stage(1, 1);
    CP_COMMIT();

    for (int kt = 0; kt < KT; kt++) {
        if (kt + 2 < KT) load_stage(kt + 2, (kt + 2) % NSTAGE);
        CP_COMMIT();
        CP_WAIT2();
        __syncthreads();
        int s = kt % NSTAGE;
        const __half* sAs = sA + s * BM * LDA;
        const __half* sBs = sB + s * BK * LDB;
#pragma unroll
        for (int ks = 0; ks < 2; ks++) {
            wmma::fragment<wmma::matrix_a, 16, 16, 16, __half, wmma::row_major> fa[2];
            wmma::fragment<wmma::matrix_b, 16, 16, 16, __half, wmma::row_major> fb[2];
            wmma::load_matrix_sync(fa[0], sAs + (wr * 32 + 0) * LDA + ks * 16, LDA);
            wmma::load_matrix_sync(fa[1], sAs + (wr * 32 + 16) * LDA + ks * 16, LDA);
            wmma::load_matrix_sync(fb[0], sBs + (ks * 16) * LDB + wc * 32, LDB);
            wmma::load_matrix_sync(fb[1], sBs + (ks * 16) * LDB + wc * 32 + 16, LDB);
            wmma::mma_sync(acc[0][0], fa[0], fb[0], acc[0][0]);
            wmma::mma_sync(acc[0][1], fa[0], fb[1], acc[0][1]);
            wmma::mma_sync(acc[1][0], fa[1], fb[0], acc[1][0]);
            wmma::mma_sync(acc[1][1], fa[1], fb[1], acc[1][1]);
        }
        __syncthreads();
    }

#pragma unroll
    for (int i = 0; i < 2; i++)
#pragma unroll
        for (int j = 0; j < 2; j++)
            wmma::store_matrix_sync(sC + (wr * 32 + i * 16) * LDC + wc * 32 + j * 16,
                                    acc[i][j], LDC, wmma::mem_row_major);
    __syncthreads();

    for (int idx = tid; idx < BM * BN; idx += 256) {
        int r = idx >> 6;
        int c = idx & 63;
        int gc = bn + c;
        if (gc >= Nd) continue;
        float v = sC[r * LDC + c];
        size_t gi = (size_t)(bm + r) * Nd + gc;
        if (epi == 1)      ((__half*)Cout)[gi] = __float2half(tanhf(v));
        else if (epi == 2) ((__half*)Cout)[gi] = __float2half(sigmoidf_(v));
        else               ((__half*)Cout)[gi] = __float2half(v);
    }
}

__global__ void __launch_bounds__(256) k_gemm_lora_up() {
    __shared__ __align__(16) unsigned char sm[SMEM_BYTES];
    int z = blockIdx.z;
    const size_t aoff[4] = {O_XW, O_XA, O_XV, O_XG};
    const size_t boff[4] = {O_W116, O_A116, O_V116, O_G116};
    const size_t coff[4] = {O_HW, O_HA, O_HV, O_HG};
    const int nd[4] = {64, 64, 32, 128};
    const int ep[4] = {1, 3, 3, 2};
    int bn = blockIdx.x * BN;
    if (bn >= nd[z]) return;
    gemm_tile((const __half*)(g_scratch + aoff[z]), (const __half*)(g_scratch + boff[z]),
              (void*)(g_scratch + coff[z]), nd[z], Cc, ep[z],
              blockIdx.y * BM, bn, sm);
}

// ---------------- per-token prepare ----------------
__global__ void k_prepare(const float* __restrict__ vfirst,
                          const float* __restrict__ w0, const float* __restrict__ a0,
                          const float* __restrict__ v0, const float* __restrict__ kkw,
                          const float* __restrict__ kaw, const float* __restrict__ rkw) {
    const float* Rf   = (const float*)(g_scratch + O_R);
    const float* Kf   = (const float*)(g_scratch + O_K);
    const float* Vf   = (const float*)(g_scratch + O_V);
    const float* WRAW = (const float*)(g_scratch + O_WRAW);
    const float* ARAW = (const float*)(g_scratch + O_ARAW);
    const float* VRAW = (const float*)(g_scratch + O_VRAW);
    float* SR  = (float*)(g_scratch + O_SR);
    float* SW  = (float*)(g_scratch + O_SW);
    float* SK  = (float*)(g_scratch + O_SK);
    float* SV  = (float*)(g_scratch + O_SV);
    float* SA  = (float*)(g_scratch + O_SA);
    float* SB_ = (float*)(g_scratch + O_SB);
    float* COEF = (float*)(g_scratch + O_COEF);

    int gw = (blockIdx.x * blockDim.x + threadIdx.x) >> 5;
    int lane = threadIdx.x & 31;
    if (gw >= Mm * Hh) return;
    int m = gw / Hh;
    int h = gw % Hh;
    int b = m >> 10;
    int t = m & (Tt - 1);
    int n = lane * 2;
    int c = h * Nn + n;
    size_t gbase = (size_t)m * Cc + c;

    float2 k2   = *(const float2*)(Kf + gbase);
    float2 kkwv = *(const float2*)(kkw + c);
    float kkx = k2.x * kkwv.x, kky = k2.y * kkwv.y;
    float ss = kkx * kkx + kky * kky;
#pragma unroll
    for (int o = 16; o; o >>= 1) ss += __shfl_xor_sync(0xffffffffu, ss, o);
    float inv = 1.f / fmaxf(sqrtf(ss), 1e-12f);

    float2 ar2 = *(const float2*)(ARAW + gbase);
    float2 a0v = *(const float2*)(a0 + c);
    float ax = sigmoidf_(a0v.x + ar2.x);
    float ay = sigmoidf_(a0v.y + ar2.y);

    float2 kav = *(const float2*)(kaw + c);
    float khx = k2.x * (1.f + (ax - 1.f) * kav.x);
    float khy = k2.y * (1.f + (ay - 1.f) * kav.y);

    float2 wr2 = *(const float2*)(WRAW + gbase);
    float2 w0v = *(const float2*)(w0 + c);
    float wx = EXP_NEG_HALF * sigmoidf_(w0v.x + wr2.x);
    float wy = EXP_NEG_HALF * sigmoidf_(w0v.y + wr2.y);

    float2 vr2 = *(const float2*)(VRAW + gbase);
    float2 v0v = *(const float2*)(v0 + c);
    float svx = sigmoidf_(v0v.x + vr2.x);
    float svy = sigmoidf_(v0v.y + vr2.y);
    float2 vv  = *(const float2*)(Vf + gbase);
    float2 vf2 = *(const float2*)(vfirst + gbase);
    float vhx = vv.x + (vf2.x - vv.x) * svx;
    float vhy = vv.y + (vf2.y - vv.y) * svy;

    float2 r2  = *(const float2*)(Rf + gbase);
    float2 rkv = *(const float2*)(rkw + c);
    float cf = r2.x * khx * rkv.x + r2.y * khy * rkv.y;
#pragma unroll
    for (int o = 16; o; o >>= 1) cf += __shfl_xor_sync(0xffffffffu, cf, o);

    int bh = b * Hh + h;
    size_t sbase = ((size_t)bh * Tt + t) * Nn + n;
    *(float2*)(SR + sbase)  = r2;
    *(float2*)(SW + sbase)  = make_float2(wx, wy);
    *(float2*)(SK + sbase)  = make_float2(khx, khy);
    *(float2*)(SV + sbase)  = make_float2(vhx, vhy);
    *(float2*)(SA + sbase)  = make_float2(-kkx * inv, -kky * inv);
    *(float2*)(SB_ + sbase) = make_float2(kkx * inv * ax, kky * inv * ay);
    if (lane == 0) COEF[(size_t)bh * Tt + t] = cf;
}

// ---------------- sequential scan over T ----------------
__global__ void __launch_bounds__(64) k_scan() {
    const float* SR  = (const float*)(g_scratch + O_SR);
    const float* SW  = (const float*)(g_scratch + O_SW);
    const float* SK  = (const float*)(g_scratch + O_SK);
    const float* SV  = (const float*)(g_scratch + O_SV);
    const float* SA  = (const float*)(g_scratch + O_SA);
    const float* SB_ = (const float*)(g_scratch + O_SB);
    float* WKV = (float*)(g_scratch + O_WKV);

    int blk = blockIdx.x;
    int bh = blk >> 3;
    int q = blk & 7;
    int tid = threadIdx.x;
    int rowl = tid >> 3;
    int cg = tid & 7;
    int row = q * 8 + rowl;
    size_t base = (size_t)bh * Tt * Nn;
    int co = cg * 8;

    float st[8];
#pragma unroll
    for (int j = 0; j < 8; j++) st[j] = 0.f;

    float4 cur[5][2], nxt[5][2];
    float cv, nv;
    {
        size_t o = base + co;
        cur[0][0] = __ldg((const float4*)(SW + o));  cur[0][1] = __ldg((const float4*)(SW + o + 4));
        cur[1][0] = __ldg((const float4*)(SA + o));  cur[1][1] = __ldg((const float4*)(SA + o + 4));
        cur[2][0] = __ldg((const float4*)(SB_ + o)); cur[2][1] = __ldg((const float4*)(SB_ + o + 4));
        cur[3][0] = __ldg((const float4*)(SK + o));  cur[3][1] = __ldg((const float4*)(SK + o + 4));
        cur[4][0] = __ldg((const float4*)(SR + o));  cur[4][1] = __ldg((const float4*)(SR + o + 4));
        cv = __ldg(SV + base + row);
    }

    for (int t = 0; t < Tt; t++) {
        int tn = (t + 1 < Tt) ? t + 1 : t;
        size_t on = base + (size_t)tn * Nn + co;
        nxt[0][0] = __ldg((const float4*)(SW + on));  nxt[0][1] = __ldg((const float4*)(SW + on + 4));
        nxt[1][0] = __ldg((const float4*)(SA + on));  nxt[1][1] = __ldg((const float4*)(SA + on + 4));
        nxt[2][0] = __ldg((const float4*)(SB_ + on)); nxt[2][1] = __ldg((const float4*)(SB_ + on + 4));
        nxt[3][0] = __ldg((const float4*)(SK + on));  nxt[3][1] = __ldg((const float4*)(SK + on + 4));
        nxt[4][0] = __ldg((const float4*)(SR + on));  nxt[4][1] = __ldg((const float4*)(SR + on + 4));
        nv = __ldg(SV + base + (size_t)tn * Nn + row);

        float sa = 0.f;
#pragma unroll
        for (int j = 0; j < 8; j++) sa = fmaf(st[j], getc(cur[1][j >> 2], j & 3), sa);
        sa += __shfl_xor_sync(0xffffffffu, sa, 1);
        sa += __shfl_xor_sync(0xffffffffu, sa, 2);
        sa += __shfl_xor_sync(0xffffffffu, sa, 4);

        float outp = 0.f;
#pragma unroll
        for (int j = 0; j < 8; j++) {
            float wj = getc(cur[0][j >> 2], j & 3);
            float bj = getc(cur[2][j >> 2], j & 3);
            float kj = getc(cur[3][j >> 2], j & 3);
            float rj = getc(cur[4][j >> 2], j & 3);
            float s = fmaf(st[j], wj, fmaf(sa, bj, cv * kj));
            st[j] = s;
            outp = fmaf(s, rj, outp);
        }
        outp += __shfl_xor_sync(0xffffffffu, outp, 1);
        outp += __shfl_xor_sync(0xffffffffu, outp, 2);
        outp += __shfl_xor_sync(0xffffffffu, outp, 4);
        if (cg == 0) WKV[base + (size_t)t * Nn + row] = outp;

#pragma unroll
        for (int v = 0; v < 5; v++) { cur[v][0] = nxt[v][0]; cur[v][1] = nxt[v][1]; }
        cv = nv;
    }
}

// ---------------- groupnorm + bonus + gate ----------------
__global__ void k_gn(const float* __restrict__ lng, const float* __restrict__ lnb) {
    const float* WKV  = (const float*)(g_scratch + O_WKV);
    const float* SV   = (const float*)(g_scratch + O_SV);
    const float* COEF = (const float*)(g_scratch + O_COEF);
    const float* GG   = (const float*)(g_scratch + O_GG);
    __half* XO = (__half*)(g_scratch + O_XO);

    int gw = (blockIdx.x * blockDim.x + threadIdx.x) >> 5;
    int lane = threadIdx.x & 31;
    if (gw >= Mm * Hh) return;
    int m = gw / Hh;
    int h = gw % Hh;
    int b = m >> 10;
    int t = m & (Tt - 1);
    int bh = b * Hh + h;
    int n = lane * 2;
    int c = h * Nn + n;
    size_t sbase = ((size_t)bh * Tt + t) * Nn + n;

    float2 x2 = *(const float2*)(WKV + sbase);
    float s1 = x2.x + x2.y;
    float s2 = x2.x * x2.x + x2.y * x2.y;
#pragma unroll
    for (int o = 16; o; o >>= 1) {
        s1 += __shfl_xor_sync(0xffffffffu, s1, o);
        s2 += __shfl_xor_sync(0xffffffffu, s2, o);
    }
    float mu = s1 * (1.f / 64.f);
    float var = s2 * (1.f / 64.f) - mu * mu;
    float inv = rsqrtf(fmaxf(var, 0.f) + LN_EPS_F);

    float2 g2v = *(const float2*)(lng + c);
    float2 b2v = *(const float2*)(lnb + c);
    float xn0 = (x2.x - mu) * inv * g2v.x + b2v.x;
    float xn1 = (x2.y - mu) * inv * g2v.y + b2v.y;

    float cf = COEF[(size_t)bh * Tt + t];
    float2 vh2 = *(const float2*)(SV + sbase);
    float xo0 = xn0 + cf * vh2.x;
    float xo1 = xn1 + cf * vh2.y;

    float2 gg2 = *(const float2*)(GG + (size_t)m * Cc + c);
    *(__half2*)(XO + (size_t)m * Cc + c) = __floats2half2_rn(xo0 * gg2.x, xo1 * gg2.y);
}

// ---------------- host launcher ----------------
static inline int cdiv_(int a, int b) { return (a + b - 1) / b; }

extern "C" void kernel_launch(void* const* d_in, const int* in_sizes, int n_in,
                              void* d_out, int out_size) {
    (void)in_sizes; (void)n_in; (void)out_size;
    const float* x       = (const float*)d_in[0];
    const float* v_first = (const float*)d_in[1];
    const float* x_r  = (const float*)d_in[2];
    const float* x_w  = (const float*)d_in[3];
    const float* x_k  = (const float*)d_in[4];
    const float* x_v  = (const float*)d_in[5];
    const float* x_a  = (const float*)d_in[6];
    const float* x_g  = (const float*)d_in[7];
    const float* w0   = (const float*)d_in[8];
    const float* w1   = (const float*)d_in[9];
    const float* a0   = (const float*)d_in[11];
    const float* a1   = (const float*)d_in[12];
    const float* v0   = (const float*)d_in[14];
    const float* v1   = (const float*)d_in[15];
    const float* g1   = (const float*)d_in[17];
    const float* k_k  = (const float*)d_in[19];
    const float* k_a  = (const float*)d_in[20];
    const float* r_k  = (const float*)d_in[21];
    const float* ln_g = (const float*)d_in[26];
    const float* ln_b = (const float*)d_in[27];

    {
        dim3 g(cdiv_(Cc * Cc / 4, 256), 12);
        k_convert_all<<<g, 256>>>((const float*)d_in[22], (const float*)d_in[23],
                                  (const float*)d_in[24], (const float*)d_in[25],
                                  w1, a1, v1, g1,
                                  (const float*)d_in[10], (const float*)d_in[13],
                                  (const float*)d_in[16], (const float*)d_in[18]);
    }

    k_mix<<<cdiv_(Mm * (Cc / 4), 256), 256>>>(x, x_r, x_w, x_k, x_v, x_a, x_g);

    {
        dim3 g(cdiv_(Cc, FBN), Mm / FBM, 3);
        k2_gemm_rkv<<<g, 256>>>();
    }
    {
        dim3 g(2, Mm / BM, 4);     // old kernel, covers N up to 128
        k_gemm_lora_up<<<g, 256>>>();
    }
    {
        dim3 g(cdiv_(Cc, FBN), Mm / FBM, 4);
        k2_gemm_down<<<g, 256>>>();
    }

    k_prepare<<<Mm * Hh / 8, 256>>>(v_first, w0, a0, v0, k_k, k_a, r_k);

    k_scan<<<Bb * Hh * (Nn / 8), 64>>>();

    k_gn<<<Mm * Hh / 8, 256>>>(ln_g, ln_b);

    {
        dim3 g(cdiv_(Cc, FBN), Mm / FBM);
        k2_gemm_out<<<g, 256>>>((float*)d_out);
    }
}

// round 6
// speedup vs baseline: 1.5538x; 1.3901x over previous
#include <cuda_runtime.h>
#include <cuda_fp16.h>
#include <mma.h>
#include <cstdint>

using namespace nvcuda;

// ---------------- problem constants ----------------
namespace {
constexpr int Bb = 4, Tt = 1024, Cc = 960, Hh = 15, Nn = 64;
constexpr int Mm = Bb * Tt;                    // 4096 tokens
constexpr float LN_EPS_F = 0.00064f;
constexpr float EXP_NEG_HALF = 0.6065306597126334f;

constexpr size_t MC  = (size_t)Mm * Cc;
constexpr size_t SZ_H_MC = MC * 2;
constexpr size_t SZ_F_MC = MC * 4;

constexpr size_t O_XR   = 0;
constexpr size_t O_XW   = O_XR + SZ_H_MC;
constexpr size_t O_XK   = O_XW + SZ_H_MC;
constexpr size_t O_XV   = O_XK + SZ_H_MC;
constexpr size_t O_XA   = O_XV + SZ_H_MC;
constexpr size_t O_XG   = O_XA + SZ_H_MC;
constexpr size_t O_WR16 = O_XG + SZ_H_MC;
constexpr size_t O_WK16 = O_WR16 + (size_t)Cc * Cc * 2;
constexpr size_t O_WV16 = O_WK16 + (size_t)Cc * Cc * 2;
constexpr size_t O_WO16 = O_WV16 + (size_t)Cc * Cc * 2;
constexpr size_t O_W116 = O_WO16 + (size_t)Cc * Cc * 2;
constexpr size_t O_A116 = O_W116 + (size_t)Cc * 64 * 2;
constexpr size_t O_V116 = O_A116 + (size_t)Cc * 64 * 2;
constexpr size_t O_G116 = O_V116 + (size_t)Cc * 32 * 2;
constexpr size_t O_W216 = O_G116 + (size_t)Cc * 128 * 2;
constexpr size_t O_A216 = O_W216 + (size_t)64 * Cc * 2;
constexpr size_t O_V216 = O_A216 + (size_t)64 * Cc * 2;
constexpr size_t O_G216 = O_V216 + (size_t)32 * Cc * 2;
constexpr size_t O_HW   = O_G216 + (size_t)128 * Cc * 2;
constexpr size_t O_HA   = O_HW + (size_t)Mm * 64 * 2;
constexpr size_t O_HV   = O_HA + (size_t)Mm * 64 * 2;
constexpr size_t O_HG   = O_HV + (size_t)Mm * 32 * 2;
constexpr size_t O_R    = O_HG + (size_t)Mm * 128 * 2;
constexpr size_t O_K    = O_R + SZ_F_MC;
constexpr size_t O_V    = O_K + SZ_F_MC;
constexpr size_t O_WRAW = O_V + SZ_F_MC;
constexpr size_t O_ARAW = O_WRAW + SZ_F_MC;
constexpr size_t O_VRAW = O_ARAW + SZ_F_MC;
constexpr size_t O_GG   = O_VRAW + SZ_F_MC;
constexpr size_t O_SR   = O_GG + SZ_F_MC;
constexpr size_t O_SW   = O_SR + SZ_F_MC;
constexpr size_t O_SK   = O_SW + SZ_F_MC;
constexpr size_t O_SV   = O_SK + SZ_F_MC;
constexpr size_t O_SA   = O_SV + SZ_F_MC;
constexpr size_t O_SB   = O_SA + SZ_F_MC;
constexpr size_t O_COEF = O_SB + SZ_F_MC;
constexpr size_t O_WKV  = O_COEF + (size_t)Bb * Hh * Tt * 4;
constexpr size_t O_XO   = O_WKV + SZ_F_MC;
constexpr size_t SCRATCH_TOTAL = O_XO + SZ_H_MC;

// old (fp16-epilogue) GEMM tile config
constexpr int BM = 128, BN = 64, BK = 32;
constexpr int LDA = 40, LDB = 72, LDC = 68, NSTAGE = 3;
constexpr int SMEM_AB = NSTAGE * (BM * LDA + BK * LDB) * 2;
constexpr int SMEM_C  = BM * LDC * 4;
constexpr int SMEM_BYTES = SMEM_AB > SMEM_C ? SMEM_AB : SMEM_C;

// new fast fp32-output GEMM config
constexpr int FBM = 128, FBN = 128, FBK = 32;
constexpr int FLDA = 40, FLDB = 136;

// scan pipeline depth
constexpr int SCAN_D = 8;
} // namespace

__device__ __align__(256) unsigned char g_scratch[SCRATCH_TOTAL];

// ---------------- helpers ----------------
__device__ __forceinline__ float sigmoidf_(float x) { return 1.f / (1.f + expf(-x)); }
__device__ __forceinline__ float getc(const float4& v, int j) {
    return j == 0 ? v.x : j == 1 ? v.y : j == 2 ? v.z : v.w;
}
__device__ __forceinline__ void cp_async16(void* smem_dst, const void* gsrc) {
    unsigned int d = (unsigned int)__cvta_generic_to_shared(smem_dst);
    asm volatile("cp.async.cg.shared.global [%0], [%1], 16;" :: "r"(d), "l"(gsrc));
}
__device__ __forceinline__ void cp_async16p(void* smem_dst, const void* gsrc, bool pred) {
    unsigned int d = (unsigned int)__cvta_generic_to_shared(smem_dst);
    int b = pred ? 16 : 0;
    asm volatile("cp.async.cg.shared.global [%0], [%1], 16, %2;" :: "r"(d), "l"(gsrc), "r"(b));
}
#define CP_COMMIT() asm volatile("cp.async.commit_group;")
#define CP_WAIT1()  asm volatile("cp.async.wait_group 1;")
#define CP_WAIT2()  asm volatile("cp.async.wait_group 2;")
#define CP_WAIT7()  asm volatile("cp.async.wait_group 7;")

// ---------------- fused weight convert ----------------
__global__ void k_convert_all(const float* p0, const float* p1, const float* p2,
                              const float* p3, const float* p4, const float* p5,
                              const float* p6, const float* p7, const float* p8,
                              const float* p9, const float* p10, const float* p11) {
    const int sizes[12] = {Cc * Cc, Cc * Cc, Cc * Cc, Cc * Cc,
                           Cc * 64, Cc * 64, Cc * 32, Cc * 128,
                           64 * Cc, 64 * Cc, 32 * Cc, 128 * Cc};
    const size_t doff[12] = {O_WR16, O_WK16, O_WV16, O_WO16,
                             O_W116, O_A116, O_V116, O_G116,
                             O_W216, O_A216, O_V216, O_G216};
    const float* srcs[12] = {p0, p1, p2, p3, p4, p5, p6, p7, p8, p9, p10, p11};
    int z = blockIdx.y;
    int n = sizes[z];
    int i = (blockIdx.x * 256 + threadIdx.x) * 4;
    if (i >= n) return;
    const float* s = srcs[z];
    __half* d = (__half*)(g_scratch + doff[z]);
    float4 v = *(const float4*)(s + i);
    *(__half2*)(d + i)     = __floats2half2_rn(v.x, v.y);
    *(__half2*)(d + i + 2) = __floats2half2_rn(v.z, v.w);
}

// ---------------- token shift + mix ----------------
__global__ void k_mix(const float* __restrict__ x,
                      const float* __restrict__ mr, const float* __restrict__ mw,
                      const float* __restrict__ mk, const float* __restrict__ mv,
                      const float* __restrict__ ma, const float* __restrict__ mg) {
    int i = blockIdx.x * blockDim.x + threadIdx.x;
    if (i >= Mm * (Cc / 4)) return;
    int m = i / (Cc / 4);
    int c = (i % (Cc / 4)) * 4;
    int t = m & (Tt - 1);
    float4 xc = *(const float4*)(x + (size_t)m * Cc + c);
    float4 xp = make_float4(0.f, 0.f, 0.f, 0.f);
    if (t > 0) xp = *(const float4*)(x + (size_t)(m - 1) * Cc + c);
    float4 dx = make_float4(xp.x - xc.x, xp.y - xc.y, xp.z - xc.z, xp.w - xc.w);

    const float* mixes[6] = {mr, mw, mk, mv, ma, mg};
    const size_t offs[6] = {O_XR, O_XW, O_XK, O_XV, O_XA, O_XG};
#pragma unroll
    for (int q = 0; q < 6; q++) {
        float4 mmv = *(const float4*)(mixes[q] + c);
        __half* out = (__half*)(g_scratch + offs[q]);
        __half2 h0 = __floats2half2_rn(xc.x + dx.x * mmv.x, xc.y + dx.y * mmv.y);
        __half2 h1 = __floats2half2_rn(xc.z + dx.z * mmv.z, xc.w + dx.w * mmv.w);
        *(__half2*)(out + (size_t)m * Cc + c)     = h0;
        *(__half2*)(out + (size_t)m * Cc + c + 2) = h1;
    }
}

// ---------------- fast fp32-output GEMM: 64x32 warp tile, direct store ----------------
__device__ __forceinline__ void gemm_fast(const __half* __restrict__ A,
                                          const __half* __restrict__ Bm,
                                          float* __restrict__ Cf,
                                          int Nd, int Kd,
                                          int bm, int bn,
                                          __half* sA, __half* sB) {
    int tid = threadIdx.x;
    int warp = tid >> 5;
    int wr = warp >> 2;
    int wc = warp & 3;
    int KT = Kd / FBK;

    auto load_stage = [&](int kt, int s) {
        const __half* Ag = A + (size_t)bm * Kd + kt * FBK;
        __half* sAs = sA + s * FBM * FLDA;
        __half* sBs = sB + s * FBK * FLDB;
#pragma unroll
        for (int u = 0; u < 2; u++) {
            int id = tid + u * 256;
            int r = id >> 2;
            int c = (id & 3) * 8;
            cp_async16(sAs + r * FLDA + c, Ag + (size_t)r * Kd + c);
        }
#pragma unroll
        for (int u = 0; u < 2; u++) {
            int id = tid + u * 256;
            int r = id >> 4;
            int c = (id & 15) * 8;
            bool p = (bn + c) < Nd;
            const __half* Bg = Bm + (size_t)(kt * FBK + r) * Nd + bn + c;
            cp_async16p(sBs + r * FLDB + c, p ? Bg : (const __half*)Bm, p);
        }
    };

    wmma::fragment<wmma::accumulator, 16, 16, 16, float> acc[4][2];
#pragma unroll
    for (int i = 0; i < 4; i++)
#pragma unroll
        for (int j = 0; j < 2; j++) wmma::fill_fragment(acc[i][j], 0.f);

    load_stage(0, 0);
    CP_COMMIT();

    for (int kt = 0; kt < KT; kt++) {
        if (kt + 1 < KT) load_stage(kt + 1, (kt + 1) & 1);
        CP_COMMIT();
        CP_WAIT1();
        __syncthreads();
        const __half* sAs = sA + (kt & 1) * FBM * FLDA;
        const __half* sBs = sB + (kt & 1) * FBK * FLDB;
#pragma unroll
        for (int ks = 0; ks < 2; ks++) {
            wmma::fragment<wmma::matrix_b, 16, 16, 16, __half, wmma::row_major> fb[2];
            wmma::load_matrix_sync(fb[0], sBs + (ks * 16) * FLDB + wc * 32, FLDB);
            wmma::load_matrix_sync(fb[1], sBs + (ks * 16) * FLDB + wc * 32 + 16, FLDB);
#pragma unroll
            for (int i = 0; i < 4; i++) {
                wmma::fragment<wmma::matrix_a, 16, 16, 16, __half, wmma::row_major> fa;
                wmma::load_matrix_sync(fa, sAs + (wr * 64 + i * 16) * FLDA + ks * 16, FLDA);
                wmma::mma_sync(acc[i][0], fa, fb[0], acc[i][0]);
                wmma::mma_sync(acc[i][1], fa, fb[1], acc[i][1]);
            }
        }
        __syncthreads();
    }

#pragma unroll
    for (int i = 0; i < 4; i++)
#pragma unroll
        for (int j = 0; j < 2; j++) {
            int gc = bn + wc * 32 + j * 16;
            if (gc < Nd)
                wmma::store_matrix_sync(Cf + (size_t)(bm + wr * 64 + i * 16) * Nd + gc,
                                        acc[i][j], Nd, wmma::mem_row_major);
        }
}

__global__ void __launch_bounds__(256, 2) k2_gemm_rkv() {
    __shared__ __align__(16) __half sA[2 * FBM * FLDA];
    __shared__ __align__(16) __half sB[2 * FBK * FLDB];
    int z = blockIdx.z;
    const size_t aoff[3] = {O_XR, O_XK, O_XV};
    const size_t boff[3] = {O_WR16, O_WK16, O_WV16};
    const size_t coff[3] = {O_R, O_K, O_V};
    gemm_fast((const __half*)(g_scratch + aoff[z]), (const __half*)(g_scratch + boff[z]),
              (float*)(g_scratch + coff[z]), Cc, Cc,
              blockIdx.y * FBM, blockIdx.x * FBN, sA, sB);
}

__global__ void __launch_bounds__(256, 2) k2_gemm_down() {
    __shared__ __align__(16) __half sA[2 * FBM * FLDA];
    __shared__ __align__(16) __half sB[2 * FBK * FLDB];
    int z = blockIdx.z;
    const size_t aoff[4] = {O_HW, O_HA, O_HV, O_HG};
    const size_t boff[4] = {O_W216, O_A216, O_V216, O_G216};
    const size_t coff[4] = {O_WRAW, O_ARAW, O_VRAW, O_GG};
    const int kd[4] = {64, 64, 32, 128};
    gemm_fast((const __half*)(g_scratch + aoff[z]), (const __half*)(g_scratch + boff[z]),
              (float*)(g_scratch + coff[z]), Cc, kd[z],
              blockIdx.y * FBM, blockIdx.x * FBN, sA, sB);
}

__global__ void __launch_bounds__(256, 2) k2_gemm_out(float* __restrict__ out) {
    __shared__ __align__(16) __half sA[2 * FBM * FLDA];
    __shared__ __align__(16) __half sB[2 * FBK * FLDB];
    gemm_fast((const __half*)(g_scratch + O_XO), (const __half*)(g_scratch + O_WO16),
              out, Cc, Cc, blockIdx.y * FBM, blockIdx.x * FBN, sA, sB);
}

// ---------------- old pipelined wmma GEMM (fp16 epilogues, lora_up only) ----------------
__device__ __forceinline__ void gemm_tile(const __half* __restrict__ A,
                                          const __half* __restrict__ Bm,
                                          void* __restrict__ Cout,
                                          int Nd, int Kd, int epi,
                                          int bm, int bn,
                                          unsigned char* smem_raw) {
    __half* sA = (__half*)smem_raw;
    __half* sB = ((__half*)smem_raw) + NSTAGE * BM * LDA;
    float*  sC = (float*)smem_raw;

    int tid = threadIdx.x;
    int warp = tid >> 5;
    int wr = warp & 3;
    int wc = warp >> 2;
    int KT = Kd / BK;

    auto load_stage = [&](int kt, int s) {
        const __half* Ag = A + (size_t)bm * Kd + kt * BK;
        __half* sAs = sA + s * BM * LDA;
        __half* sBs = sB + s * BK * LDB;
#pragma unroll
        for (int u = 0; u < 2; u++) {
            int id = tid + u * 256;
            int r = id >> 2;
            int c = (id & 3) * 8;
            cp_async16(sAs + r * LDA + c, Ag + (size_t)r * Kd + c);
        }
        {
            int r = tid >> 3;
            int c = (tid & 7) * 8;
            bool p = (bn + c) < Nd;
            const __half* Bg = Bm + (size_t)(kt * BK + r) * Nd + bn + c;
            cp_async16p(sBs + r * LDB + c, p ? Bg : (const __half*)Bm, p);
        }
    };

    wmma::fragment<wmma::accumulator, 16, 16, 16, float> acc[2][2];
#pragma unroll
    for (int i = 0; i < 2; i++)
#pragma unroll
        for (int j = 0; j < 2; j++) wmma::fill_fragment(acc[i][j], 0.f);

    load_stage(0, 0);
    CP_COMMIT();
    if (KT > 1) load_stage(1, 1);
    CP_COMMIT();

    for (int kt = 0; kt < KT; kt++) {
        if (kt + 2 < KT) load_stage(kt + 2, (kt + 2) % NSTAGE);
        CP_COMMIT();
        CP_WAIT2();
        __syncthreads();
        int s = kt % NSTAGE;
        const __half* sAs = sA + s * BM * LDA;
        const __half* sBs = sB + s * BK * LDB;
#pragma unroll
        for (int ks = 0; ks < 2; ks++) {
            wmma::fragment<wmma::matrix_a, 16, 16, 16, __half, wmma::row_major> fa[2];
            wmma::fragment<wmma::matrix_b, 16, 16, 16, __half, wmma::row_major> fb[2];
            wmma::load_matrix_sync(fa[0], sAs + (wr * 32 + 0) * LDA + ks * 16, LDA);
            wmma::load_matrix_sync(fa[1], sAs + (wr * 32 + 16) * LDA + ks * 16, LDA);
            wmma::load_matrix_sync(fb[0], sBs + (ks * 16) * LDB + wc * 32, LDB);
            wmma::load_matrix_sync(fb[1], sBs + (ks * 16) * LDB + wc * 32 + 16, LDB);
            wmma::mma_sync(acc[0][0], fa[0], fb[0], acc[0][0]);
            wmma::mma_sync(acc[0][1], fa[0], fb[1], acc[0][1]);
            wmma::mma_sync(acc[1][0], fa[1], fb[0], acc[1][0]);
            wmma::mma_sync(acc[1][1], fa[1], fb[1], acc[1][1]);
        }
        __syncthreads();
    }

#pragma unroll
    for (int i = 0; i < 2; i++)
#pragma unroll
        for (int j = 0; j < 2; j++)
            wmma::store_matrix_sync(sC + (wr * 32 + i * 16) * LDC + wc * 32 + j * 16,
                                    acc[i][j], LDC, wmma::mem_row_major);
    __syncthreads();

    for (int idx = tid; idx < BM * BN; idx += 256) {
        int r = idx >> 6;
        int c = idx & 63;
        int gc = bn + c;
        if (gc >= Nd) continue;
        float v = sC[r * LDC + c];
        size_t gi = (size_t)(bm + r) * Nd + gc;
        if (epi == 1)      ((__half*)Cout)[gi] = __float2half(tanhf(v));
        else if (epi == 2) ((__half*)Cout)[gi] = __float2half(sigmoidf_(v));
        else               ((__half*)Cout)[gi] = __float2half(v);
    }
}

__global__ void __launch_bounds__(256) k_gemm_lora_up() {
    __shared__ __align__(16) unsigned char sm[SMEM_BYTES];
    int z = blockIdx.z;
    const size_t aoff[4] = {O_XW, O_XA, O_XV, O_XG};
    const size_t boff[4] = {O_W116, O_A116, O_V116, O_G116};
    const size_t coff[4] = {O_HW, O_HA, O_HV, O_HG};
    const int nd[4] = {64, 64, 32, 128};
    const int ep[4] = {1, 3, 3, 2};
    int bn = blockIdx.x * BN;
    if (bn >= nd[z]) return;
    gemm_tile((const __half*)(g_scratch + aoff[z]), (const __half*)(g_scratch + boff[z]),
              (void*)(g_scratch + coff[z]), nd[z], Cc, ep[z],
              blockIdx.y * BM, bn, sm);
}

// ---------------- per-token prepare ----------------
__global__ void k_prepare(const float* __restrict__ vfirst,
                          const float* __restrict__ w0, const float* __restrict__ a0,
                          const float* __restrict__ v0, const float* __restrict__ kkw,
                          const float* __restrict__ kaw, const float* __restrict__ rkw) {
    const float* Rf   = (const float*)(g_scratch + O_R);
    const float* Kf   = (const float*)(g_scratch + O_K);
    const float* Vf   = (const float*)(g_scratch + O_V);
    const float* WRAW = (const float*)(g_scratch + O_WRAW);
    const float* ARAW = (const float*)(g_scratch + O_ARAW);
    const float* VRAW = (const float*)(g_scratch + O_VRAW);
    float* SR  = (float*)(g_scratch + O_SR);
    float* SW  = (float*)(g_scratch + O_SW);
    float* SK  = (float*)(g_scratch + O_SK);
    float* SV  = (float*)(g_scratch + O_SV);
    float* SA  = (float*)(g_scratch + O_SA);
    float* SB_ = (float*)(g_scratch + O_SB);
    float* COEF = (float*)(g_scratch + O_COEF);

    int gw = (blockIdx.x * blockDim.x + threadIdx.x) >> 5;
    int lane = threadIdx.x & 31;
    if (gw >= Mm * Hh) return;
    int m = gw / Hh;
    int h = gw % Hh;
    int b = m >> 10;
    int t = m & (Tt - 1);
    int n = lane * 2;
    int c = h * Nn + n;
    size_t gbase = (size_t)m * Cc + c;

    float2 k2   = *(const float2*)(Kf + gbase);
    float2 kkwv = *(const float2*)(kkw + c);
    float kkx = k2.x * kkwv.x, kky = k2.y * kkwv.y;
    float ss = kkx * kkx + kky * kky;
#pragma unroll
    for (int o = 16; o; o >>= 1) ss += __shfl_xor_sync(0xffffffffu, ss, o);
    float inv = 1.f / fmaxf(sqrtf(ss), 1e-12f);

    float2 ar2 = *(const float2*)(ARAW + gbase);
    float2 a0v = *(const float2*)(a0 + c);
    float ax = sigmoidf_(a0v.x + ar2.x);
    float ay = sigmoidf_(a0v.y + ar2.y);

    float2 kav = *(const float2*)(kaw + c);
    float khx = k2.x * (1.f + (ax - 1.f) * kav.x);
    float khy = k2.y * (1.f + (ay - 1.f) * kav.y);

    float2 wr2 = *(const float2*)(WRAW + gbase);
    float2 w0v = *(const float2*)(w0 + c);
    float wx = EXP_NEG_HALF * sigmoidf_(w0v.x + wr2.x);
    float wy = EXP_NEG_HALF * sigmoidf_(w0v.y + wr2.y);

    float2 vr2 = *(const float2*)(VRAW + gbase);
    float2 v0v = *(const float2*)(v0 + c);
    float svx = sigmoidf_(v0v.x + vr2.x);
    float svy = sigmoidf_(v0v.y + vr2.y);
    float2 vv  = *(const float2*)(Vf + gbase);
    float2 vf2 = *(const float2*)(vfirst + gbase);
    float vhx = vv.x + (vf2.x - vv.x) * svx;
    float vhy = vv.y + (vf2.y - vv.y) * svy;

    float2 r2  = *(const float2*)(Rf + gbase);
    float2 rkv = *(const float2*)(rkw + c);
    float cf = r2.x * khx * rkv.x + r2.y * khy * rkv.y;
#pragma unroll
    for (int o = 16; o; o >>= 1) cf += __shfl_xor_sync(0xffffffffu, cf, o);

    int bh = b * Hh + h;
    size_t sbase = ((size_t)bh * Tt + t) * Nn + n;
    *(float2*)(SR + sbase)  = r2;
    *(float2*)(SW + sbase)  = make_float2(wx, wy);
    *(float2*)(SK + sbase)  = make_float2(khx, khy);
    *(float2*)(SV + sbase)  = make_float2(vhx, vhy);
    *(float2*)(SA + sbase)  = make_float2(-kkx * inv, -kky * inv);
    *(float2*)(SB_ + sbase) = make_float2(kkx * inv * ax, kky * inv * ay);
    if (lane == 0) COEF[(size_t)bh * Tt + t] = cf;
}

// ---------------- sequential scan over T (smem cp.async pipeline) ----------------
// grid = 60 bh * 8 q = 480 blocks; block = 64 threads (8 rows x 8 col-groups)
// smem ring: SCAN_D stages x [W|A|B|K|R|V] x 64 floats
__global__ void __launch_bounds__(64) k_scan() {
    __shared__ __align__(16) float sbuf[SCAN_D][6 * 64];

    const float* gptr[6];
    gptr[0] = (const float*)(g_scratch + O_SW);
    gptr[1] = (const float*)(g_scratch + O_SA);
    gptr[2] = (const float*)(g_scratch + O_SB);
    gptr[3] = (const float*)(g_scratch + O_SK);
    gptr[4] = (const float*)(g_scratch + O_SR);
    gptr[5] = (const float*)(g_scratch + O_SV);
    float* WKV = (float*)(g_scratch + O_WKV);

    int blk = blockIdx.x;
    int bh = blk >> 3;
    int q = blk & 7;
    int tid = threadIdx.x;
    int rowl = tid >> 3;
    int cg = tid & 7;
    int row = q * 8 + rowl;
    size_t base = (size_t)bh * Tt * Nn;
    int co = cg * 8;

    auto issue_stage = [&](int t) {
        int slot = t & (SCAN_D - 1);
        // 6 arrays x 64 floats = 96 chunks of 16B; 64 threads
#pragma unroll
        for (int c = tid; c < 96; c += 64) {
            int a = c >> 4;
            int off = (c & 15) * 4;
            cp_async16(&sbuf[slot][a * 64 + off],
                       gptr[a] + base + (size_t)t * Nn + off);
        }
    };

    // prologue: stages 0..D-2, one commit group each
#pragma unroll
    for (int s = 0; s < SCAN_D - 1; s++) {
        issue_stage(s);
        CP_COMMIT();
    }

    float st[8];
#pragma unroll
    for (int j = 0; j < 8; j++) st[j] = 0.f;

    for (int t = 0; t < Tt; t++) {
        // (a) all threads finished reading stage t-1 -> safe to overwrite its slot
        __syncthreads();
        int tp = t + SCAN_D - 1;
        if (tp < Tt) issue_stage(tp);
        CP_COMMIT();
        CP_WAIT7();          // stage t arrived (all but 7 newest groups done)
        __syncthreads();     // cross-thread visibility of stage t

        const float* S = sbuf[t & (SCAN_D - 1)];
        float4 wv0 = *(const float4*)(S + 0 * 64 + co);
        float4 wv1 = *(const float4*)(S + 0 * 64 + co + 4);
        float4 av0 = *(const float4*)(S + 1 * 64 + co);
        float4 av1 = *(const float4*)(S + 1 * 64 + co + 4);
        float4 bv0 = *(const float4*)(S + 2 * 64 + co);
        float4 bv1 = *(const float4*)(S + 2 * 64 + co + 4);
        float4 kv0 = *(const float4*)(S + 3 * 64 + co);
        float4 kv1 = *(const float4*)(S + 3 * 64 + co + 4);
        float4 rv0 = *(const float4*)(S + 4 * 64 + co);
        float4 rv1 = *(const float4*)(S + 4 * 64 + co + 4);
        float cv = S[5 * 64 + row];

        float sa = 0.f;
#pragma unroll
        for (int j = 0; j < 8; j++)
            sa = fmaf(st[j], getc(j < 4 ? av0 : av1, j & 3), sa);
        sa += __shfl_xor_sync(0xffffffffu, sa, 1);
        sa += __shfl_xor_sync(0xffffffffu, sa, 2);
        sa += __shfl_xor_sync(0xffffffffu, sa, 4);

        float outp = 0.f;
#pragma unroll
        for (int j = 0; j < 8; j++) {
            float wj = getc(j < 4 ? wv0 : wv1, j & 3);
            float bj = getc(j < 4 ? bv0 : bv1, j & 3);
            float kj = getc(j < 4 ? kv0 : kv1, j & 3);
            float rj = getc(j < 4 ? rv0 : rv1, j & 3);
            float s = fmaf(st[j], wj, fmaf(sa, bj, cv * kj));
            st[j] = s;
            outp = fmaf(s, rj, outp);
        }
        outp += __shfl_xor_sync(0xffffffffu, outp, 1);
        outp += __shfl_xor_sync(0xffffffffu, outp, 2);
        outp += __shfl_xor_sync(0xffffffffu, outp, 4);
        if (cg == 0) WKV[base + (size_t)t * Nn + row] = outp;
    }
}

// ---------------- groupnorm + bonus + gate ----------------
__global__ void k_gn(const float* __restrict__ lng, const float* __restrict__ lnb) {
    const float* WKV  = (const float*)(g_scratch + O_WKV);
    const float* SV   = (const float*)(g_scratch + O_SV);
    const float* COEF = (const float*)(g_scratch + O_COEF);
    const float* GG   = (const float*)(g_scratch + O_GG);
    __half* XO = (__half*)(g_scratch + O_XO);

    int gw = (blockIdx.x * blockDim.x + threadIdx.x) >> 5;
    int lane = threadIdx.x & 31;
    if (gw >= Mm * Hh) return;
    int m = gw / Hh;
    int h = gw % Hh;
    int b = m >> 10;
    int t = m & (Tt - 1);
    int bh = b * Hh + h;
    int n = lane * 2;
    int c = h * Nn + n;
    size_t sbase = ((size_t)bh * Tt + t) * Nn + n;

    float2 x2 = *(const float2*)(WKV + sbase);
    float s1 = x2.x + x2.y;
    float s2 = x2.x * x2.x + x2.y * x2.y;
#pragma unroll
    for (int o = 16; o; o >>= 1) {
        s1 += __shfl_xor_sync(0xffffffffu, s1, o);
        s2 += __shfl_xor_sync(0xffffffffu, s2, o);
    }
    float mu = s1 * (1.f / 64.f);
    float var = s2 * (1.f / 64.f) - mu * mu;
    float inv = rsqrtf(fmaxf(var, 0.f) + LN_EPS_F);

    float2 g2v = *(const float2*)(lng + c);
    float2 b2v = *(const float2*)(lnb + c);
    float xn0 = (x2.x - mu) * inv * g2v.x + b2v.x;
    float xn1 = (x2.y - mu) * inv * g2v.y + b2v.y;

    float cf = COEF[(size_t)bh * Tt + t];
    float2 vh2 = *(const float2*)(SV + sbase);
    float xo0 = xn0 + cf * vh2.x;
    float xo1 = xn1 + cf * vh2.y;

    float2 gg2 = *(const float2*)(GG + (size_t)m * Cc + c);
    *(__half2*)(XO + (size_t)m * Cc + c) = __floats2half2_rn(xo0 * gg2.x, xo1 * gg2.y);
}

// ---------------- host launcher ----------------
static inline int cdiv_(int a, int b) { return (a + b - 1) / b; }

extern "C" void kernel_launch(void* const* d_in, const int* in_sizes, int n_in,
                              void* d_out, int out_size) {
    (void)in_sizes; (void)n_in; (void)out_size;
    const float* x       = (const float*)d_in[0];
    const float* v_first = (const float*)d_in[1];
    const float* x_r  = (const float*)d_in[2];
    const float* x_w  = (const float*)d_in[3];
    const float* x_k  = (const float*)d_in[4];
    const float* x_v  = (const float*)d_in[5];
    const float* x_a  = (const float*)d_in[6];
    const float* x_g  = (const float*)d_in[7];
    const float* w0   = (const float*)d_in[8];
    const float* w1   = (const float*)d_in[9];
    const float* a0   = (const float*)d_in[11];
    const float* a1   = (const float*)d_in[12];
    const float* v0   = (const float*)d_in[14];
    const float* v1   = (const float*)d_in[15];
    const float* g1   = (const float*)d_in[17];
    const float* k_k  = (const float*)d_in[19];
    const float* k_a  = (const float*)d_in[20];
    const float* r_k  = (const float*)d_in[21];
    const float* ln_g = (const float*)d_in[26];
    const float* ln_b = (const float*)d_in[27];

    {
        dim3 g(cdiv_(Cc * Cc / 4, 256), 12);
        k_convert_all<<<g, 256>>>((const float*)d_in[22], (const float*)d_in[23],
                                  (const float*)d_in[24], (const float*)d_in[25],
                                  w1, a1, v1, g1,
                                  (const float*)d_in[10], (const float*)d_in[13],
                                  (const float*)d_in[16], (const float*)d_in[18]);
    }

    k_mix<<<cdiv_(Mm * (Cc / 4), 256), 256>>>(x, x_r, x_w, x_k, x_v, x_a, x_g);

    {
        dim3 g(cdiv_(Cc, FBN), Mm / FBM, 3);
        k2_gemm_rkv<<<g, 256>>>();
    }
    {
        dim3 g(2, Mm / BM, 4);
        k_gemm_lora_up<<<g, 256>>>();
    }
    {
        dim3 g(cdiv_(Cc, FBN), Mm / FBM, 4);
        k2_gemm_down<<<g, 256>>>();
    }

    k_prepare<<<Mm * Hh / 8, 256>>>(v_first, w0, a0, v0, k_k, k_a, r_k);

    k_scan<<<Bb * Hh * (Nn / 8), 64>>>();

    k_gn<<<Mm * Hh / 8, 256>>>(ln_g, ln_b);

    {
        dim3 g(cdiv_(Cc, FBN), Mm / FBM);
        k2_gemm_out<<<g, 256>>>((float*)d_out);
    }
}

// round 7
// speedup vs baseline: 1.5707x; 1.0109x over previous
#include <cuda_runtime.h>
#include <cuda_fp16.h>
#include <mma.h>
#include <cstdint>

using namespace nvcuda;

// ---------------- problem constants ----------------
namespace {
constexpr int Bb = 4, Tt = 1024, Cc = 960, Hh = 15, Nn = 64;
constexpr int Mm = Bb * Tt;                    // 4096 tokens
constexpr float LN_EPS_F = 0.00064f;
constexpr float EXP_NEG_HALF = 0.6065306597126334f;

constexpr size_t MC  = (size_t)Mm * Cc;
constexpr size_t SZ_H_MC = MC * 2;
constexpr size_t SZ_F_MC = MC * 4;

constexpr size_t O_XR   = 0;
constexpr size_t O_XW   = O_XR + SZ_H_MC;
constexpr size_t O_XK   = O_XW + SZ_H_MC;
constexpr size_t O_XV   = O_XK + SZ_H_MC;
constexpr size_t O_XA   = O_XV + SZ_H_MC;
constexpr size_t O_XG   = O_XA + SZ_H_MC;
constexpr size_t O_WR16 = O_XG + SZ_H_MC;
constexpr size_t O_WK16 = O_WR16 + (size_t)Cc * Cc * 2;
constexpr size_t O_WV16 = O_WK16 + (size_t)Cc * Cc * 2;
constexpr size_t O_WO16 = O_WV16 + (size_t)Cc * Cc * 2;
constexpr size_t O_W116 = O_WO16 + (size_t)Cc * Cc * 2;
constexpr size_t O_A116 = O_W116 + (size_t)Cc * 64 * 2;
constexpr size_t O_V116 = O_A116 + (size_t)Cc * 64 * 2;
constexpr size_t O_G116 = O_V116 + (size_t)Cc * 32 * 2;
constexpr size_t O_W216 = O_G116 + (size_t)Cc * 128 * 2;
constexpr size_t O_A216 = O_W216 + (size_t)64 * Cc * 2;
constexpr size_t O_V216 = O_A216 + (size_t)64 * Cc * 2;
constexpr size_t O_G216 = O_V216 + (size_t)32 * Cc * 2;
constexpr size_t O_HW   = O_G216 + (size_t)128 * Cc * 2;
constexpr size_t O_HA   = O_HW + (size_t)Mm * 64 * 2;
constexpr size_t O_HV   = O_HA + (size_t)Mm * 64 * 2;
constexpr size_t O_HG   = O_HV + (size_t)Mm * 32 * 2;
constexpr size_t O_R    = O_HG + (size_t)Mm * 128 * 2;
constexpr size_t O_K    = O_R + SZ_F_MC;
constexpr size_t O_V    = O_K + SZ_F_MC;
constexpr size_t O_WRAW = O_V + SZ_F_MC;
constexpr size_t O_ARAW = O_WRAW + SZ_F_MC;
constexpr size_t O_VRAW = O_ARAW + SZ_F_MC;
constexpr size_t O_GG   = O_VRAW + SZ_F_MC;
constexpr size_t O_SR   = O_GG + SZ_F_MC;
constexpr size_t O_SW   = O_SR + SZ_F_MC;
constexpr size_t O_SK   = O_SW + SZ_F_MC;
constexpr size_t O_SV   = O_SK + SZ_F_MC;
constexpr size_t O_SA   = O_SV + SZ_F_MC;
constexpr size_t O_SB   = O_SA + SZ_F_MC;
constexpr size_t O_COEF = O_SB + SZ_F_MC;
constexpr size_t O_WKV  = O_COEF + (size_t)Bb * Hh * Tt * 4;
constexpr size_t O_XO   = O_WKV + SZ_F_MC;
constexpr size_t SCRATCH_TOTAL = O_XO + SZ_H_MC;

// fast GEMM config (128x128 CTA tile, 8 warps 2Mx4N, 64x32 warp tile)
constexpr int FBM = 128, FBN = 128, FBK = 32;
constexpr int FLDA = 40, FLDB = 136;
constexpr int NSTG = 3;
constexpr int STAGE_A = FBM * FLDA;            // halves
constexpr int STAGE_B = FBK * FLDB;            // halves
constexpr int K2_SMEM = NSTG * (STAGE_A + STAGE_B) * 2;     // 56832 B
constexpr int UPLDC = 132;
constexpr int UP_SMEM = (FBM * UPLDC * 4) > K2_SMEM ? (FBM * UPLDC * 4) : K2_SMEM; // 67584 B

// scan pipeline depth
constexpr int SCAN_D = 8;
} // namespace

__device__ __align__(256) unsigned char g_scratch[SCRATCH_TOTAL];

// ---------------- helpers ----------------
__device__ __forceinline__ float sigmoidf_(float x) { return 1.f / (1.f + expf(-x)); }
__device__ __forceinline__ float getc(const float4& v, int j) {
    return j == 0 ? v.x : j == 1 ? v.y : j == 2 ? v.z : v.w;
}
__device__ __forceinline__ void cp_async16(void* smem_dst, const void* gsrc) {
    unsigned int d = (unsigned int)__cvta_generic_to_shared(smem_dst);
    asm volatile("cp.async.cg.shared.global [%0], [%1], 16;" :: "r"(d), "l"(gsrc));
}
__device__ __forceinline__ void cp_async16p(void* smem_dst, const void* gsrc, bool pred) {
    unsigned int d = (unsigned int)__cvta_generic_to_shared(smem_dst);
    int b = pred ? 16 : 0;
    asm volatile("cp.async.cg.shared.global [%0], [%1], 16, %2;" :: "r"(d), "l"(gsrc), "r"(b));
}
#define CP_COMMIT() asm volatile("cp.async.commit_group;")
#define CP_WAIT2()  asm volatile("cp.async.wait_group 2;")
#define CP_WAIT7()  asm volatile("cp.async.wait_group 7;")

// ---------------- fused weight convert ----------------
__global__ void k_convert_all(const float* p0, const float* p1, const float* p2,
                              const float* p3, const float* p4, const float* p5,
                              const float* p6, const float* p7, const float* p8,
                              const float* p9, const float* p10, const float* p11) {
    const int sizes[12] = {Cc * Cc, Cc * Cc, Cc * Cc, Cc * Cc,
                           Cc * 64, Cc * 64, Cc * 32, Cc * 128,
                           64 * Cc, 64 * Cc, 32 * Cc, 128 * Cc};
    const size_t doff[12] = {O_WR16, O_WK16, O_WV16, O_WO16,
                             O_W116, O_A116, O_V116, O_G116,
                             O_W216, O_A216, O_V216, O_G216};
    const float* srcs[12] = {p0, p1, p2, p3, p4, p5, p6, p7, p8, p9, p10, p11};
    int z = blockIdx.y;
    int n = sizes[z];
    int i = (blockIdx.x * 256 + threadIdx.x) * 4;
    if (i >= n) return;
    const float* s = srcs[z];
    __half* d = (__half*)(g_scratch + doff[z]);
    float4 v = *(const float4*)(s + i);
    *(__half2*)(d + i)     = __floats2half2_rn(v.x, v.y);
    *(__half2*)(d + i + 2) = __floats2half2_rn(v.z, v.w);
}

// ---------------- token shift + mix ----------------
__global__ void k_mix(const float* __restrict__ x,
                      const float* __restrict__ mr, const float* __restrict__ mw,
                      const float* __restrict__ mk, const float* __restrict__ mv,
                      const float* __restrict__ ma, const float* __restrict__ mg) {
    int i = blockIdx.x * blockDim.x + threadIdx.x;
    if (i >= Mm * (Cc / 4)) return;
    int m = i / (Cc / 4);
    int c = (i % (Cc / 4)) * 4;
    int t = m & (Tt - 1);
    float4 xc = *(const float4*)(x + (size_t)m * Cc + c);
    float4 xp = make_float4(0.f, 0.f, 0.f, 0.f);
    if (t > 0) xp = *(const float4*)(x + (size_t)(m - 1) * Cc + c);
    float4 dx = make_float4(xp.x - xc.x, xp.y - xc.y, xp.z - xc.z, xp.w - xc.w);

    const float* mixes[6] = {mr, mw, mk, mv, ma, mg};
    const size_t offs[6] = {O_XR, O_XW, O_XK, O_XV, O_XA, O_XG};
#pragma unroll
    for (int q = 0; q < 6; q++) {
        float4 mmv = *(const float4*)(mixes[q] + c);
        __half* out = (__half*)(g_scratch + offs[q]);
        __half2 h0 = __floats2half2_rn(xc.x + dx.x * mmv.x, xc.y + dx.y * mmv.y);
        __half2 h1 = __floats2half2_rn(xc.z + dx.z * mmv.z, xc.w + dx.w * mmv.w);
        *(__half2*)(out + (size_t)m * Cc + c)     = h0;
        *(__half2*)(out + (size_t)m * Cc + c + 2) = h1;
    }
}

// ---------------- fast GEMM compute core: 3-stage cp.async, 64x32 warp tile ----------------
__device__ __forceinline__ void gemm_core(const __half* __restrict__ A,
                                          const __half* __restrict__ Bm,
                                          int Nd, int Kd, int bm, int bn,
                                          __half* sA, __half* sB,
                                          wmma::fragment<wmma::accumulator, 16, 16, 16, float> (&acc)[4][2]) {
    int tid = threadIdx.x;
    int warp = tid >> 5;
    int wr = warp >> 2;
    int wc = warp & 3;
    int KT = Kd / FBK;

    auto load_stage = [&](int kt, int s) {
        const __half* Ag = A + (size_t)bm * Kd + kt * FBK;
        __half* sAs = sA + s * STAGE_A;
        __half* sBs = sB + s * STAGE_B;
#pragma unroll
        for (int u = 0; u < 2; u++) {
            int id = tid + u * 256;
            int r = id >> 2;
            int c = (id & 3) * 8;
            cp_async16(sAs + r * FLDA + c, Ag + (size_t)r * Kd + c);
        }
#pragma unroll
        for (int u = 0; u < 2; u++) {
            int id = tid + u * 256;
            int r = id >> 4;
            int c = (id & 15) * 8;
            bool p = (bn + c) < Nd;
            const __half* Bg = Bm + (size_t)(kt * FBK + r) * Nd + bn + c;
            cp_async16p(sBs + r * FLDB + c, p ? Bg : (const __half*)Bm, p);
        }
    };

#pragma unroll
    for (int i = 0; i < 4; i++)
#pragma unroll
        for (int j = 0; j < 2; j++) wmma::fill_fragment(acc[i][j], 0.f);

    load_stage(0, 0);
    CP_COMMIT();
    if (KT > 1) load_stage(1, 1);
    CP_COMMIT();

    for (int kt = 0; kt < KT; kt++) {
        if (kt + 2 < KT) load_stage(kt + 2, (kt + 2) % NSTG);
        CP_COMMIT();
        CP_WAIT2();
        __syncthreads();
        const __half* sAs = sA + (kt % NSTG) * STAGE_A;
        const __half* sBs = sB + (kt % NSTG) * STAGE_B;
#pragma unroll
        for (int ks = 0; ks < 2; ks++) {
            wmma::fragment<wmma::matrix_b, 16, 16, 16, __half, wmma::row_major> fb[2];
            wmma::load_matrix_sync(fb[0], sBs + (ks * 16) * FLDB + wc * 32, FLDB);
            wmma::load_matrix_sync(fb[1], sBs + (ks * 16) * FLDB + wc * 32 + 16, FLDB);
#pragma unroll
            for (int i = 0; i < 4; i++) {
                wmma::fragment<wmma::matrix_a, 16, 16, 16, __half, wmma::row_major> fa;
                wmma::load_matrix_sync(fa, sAs + (wr * 64 + i * 16) * FLDA + ks * 16, FLDA);
                wmma::mma_sync(acc[i][0], fa, fb[0], acc[i][0]);
                wmma::mma_sync(acc[i][1], fa, fb[1], acc[i][1]);
            }
        }
        __syncthreads();
    }
}

// fp32 direct-store wrapper
__device__ __forceinline__ void gemm_fast_f32(const __half* A, const __half* Bm,
                                              float* Cf, int Nd, int Kd,
                                              int bm, int bn, __half* sA, __half* sB) {
    wmma::fragment<wmma::accumulator, 16, 16, 16, float> acc[4][2];
    gemm_core(A, Bm, Nd, Kd, bm, bn, sA, sB, acc);
    int warp = threadIdx.x >> 5;
    int wr = warp >> 2;
    int wc = warp & 3;
#pragma unroll
    for (int i = 0; i < 4; i++)
#pragma unroll
        for (int j = 0; j < 2; j++) {
            int gc = bn + wc * 32 + j * 16;
            if (gc < Nd)
                wmma::store_matrix_sync(Cf + (size_t)(bm + wr * 64 + i * 16) * Nd + gc,
                                        acc[i][j], Nd, wmma::mem_row_major);
        }
}

__global__ void __launch_bounds__(256, 2) k2_gemm_rkv() {
    extern __shared__ __align__(16) unsigned char dyn[];
    __half* sA = (__half*)dyn;
    __half* sB = sA + NSTG * STAGE_A;
    int z = blockIdx.z;
    const size_t aoff[3] = {O_XR, O_XK, O_XV};
    const size_t boff[3] = {O_WR16, O_WK16, O_WV16};
    const size_t coff[3] = {O_R, O_K, O_V};
    gemm_fast_f32((const __half*)(g_scratch + aoff[z]), (const __half*)(g_scratch + boff[z]),
                  (float*)(g_scratch + coff[z]), Cc, Cc,
                  blockIdx.y * FBM, blockIdx.x * FBN, sA, sB);
}

__global__ void __launch_bounds__(256, 2) k2_gemm_down() {
    extern __shared__ __align__(16) unsigned char dyn[];
    __half* sA = (__half*)dyn;
    __half* sB = sA + NSTG * STAGE_A;
    int z = blockIdx.z;
    const size_t aoff[4] = {O_HW, O_HA, O_HV, O_HG};
    const size_t boff[4] = {O_W216, O_A216, O_V216, O_G216};
    const size_t coff[4] = {O_WRAW, O_ARAW, O_VRAW, O_GG};
    const int kd[4] = {64, 64, 32, 128};
    gemm_fast_f32((const __half*)(g_scratch + aoff[z]), (const __half*)(g_scratch + boff[z]),
                  (float*)(g_scratch + coff[z]), Cc, kd[z],
                  blockIdx.y * FBM, blockIdx.x * FBN, sA, sB);
}

__global__ void __launch_bounds__(256, 2) k2_gemm_out(float* __restrict__ out) {
    extern __shared__ __align__(16) unsigned char dyn[];
    __half* sA = (__half*)dyn;
    __half* sB = sA + NSTG * STAGE_A;
    gemm_fast_f32((const __half*)(g_scratch + O_XO), (const __half*)(g_scratch + O_WO16),
                  out, Cc, Cc, blockIdx.y * FBM, blockIdx.x * FBN, sA, sB);
}

// lora-up: fp16 + activation epilogue via smem staging
__global__ void __launch_bounds__(256, 2) k2_gemm_up() {
    extern __shared__ __align__(16) unsigned char dyn[];
    __half* sA = (__half*)dyn;
    __half* sB = sA + NSTG * STAGE_A;
    float*  sC = (float*)dyn;

    int z = blockIdx.z;
    const size_t aoff[4] = {O_XW, O_XA, O_XV, O_XG};
    const size_t boff[4] = {O_W116, O_A116, O_V116, O_G116};
    const size_t coff[4] = {O_HW, O_HA, O_HV, O_HG};
    const int ndA[4] = {64, 64, 32, 128};
    const int epA[4] = {1, 3, 3, 2};
    int Nd = ndA[z];
    int epi = epA[z];
    int bm = blockIdx.y * FBM;

    wmma::fragment<wmma::accumulator, 16, 16, 16, float> acc[4][2];
    gemm_core((const __half*)(g_scratch + aoff[z]), (const __half*)(g_scratch + boff[z]),
              Nd, Cc, bm, 0, sA, sB, acc);

    int tid = threadIdx.x;
    int warp = tid >> 5;
    int wr = warp >> 2;
    int wc = warp & 3;
    // loop above ended with __syncthreads -> safe to reuse dyn as sC
#pragma unroll
    for (int i = 0; i < 4; i++)
#pragma unroll
        for (int j = 0; j < 2; j++)
            wmma::store_matrix_sync(sC + (wr * 64 + i * 16) * UPLDC + wc * 32 + j * 16,
                                    acc[i][j], UPLDC, wmma::mem_row_major);
    __syncthreads();

    __half* Cout = (__half*)(g_scratch + coff[z]);
    for (int idx = tid; idx < FBM * 128; idx += 256) {
        int r = idx >> 7;
        int c = idx & 127;
        if (c >= Nd) continue;
        float v = sC[r * UPLDC + c];
        if (epi == 1)      v = tanhf(v);
        else if (epi == 2) v = sigmoidf_(v);
        Cout[(size_t)(bm + r) * Nd + c] = __float2half(v);
    }
}

// ---------------- per-token prepare ----------------
__global__ void k_prepare(const float* __restrict__ vfirst,
                          const float* __restrict__ w0, const float* __restrict__ a0,
                          const float* __restrict__ v0, const float* __restrict__ kkw,
                          const float* __restrict__ kaw, const float* __restrict__ rkw) {
    const float* Rf   = (const float*)(g_scratch + O_R);
    const float* Kf   = (const float*)(g_scratch + O_K);
    const float* Vf   = (const float*)(g_scratch + O_V);
    const float* WRAW = (const float*)(g_scratch + O_WRAW);
    const float* ARAW = (const float*)(g_scratch + O_ARAW);
    const float* VRAW = (const float*)(g_scratch + O_VRAW);
    float* SR  = (float*)(g_scratch + O_SR);
    float* SW  = (float*)(g_scratch + O_SW);
    float* SK  = (float*)(g_scratch + O_SK);
    float* SV  = (float*)(g_scratch + O_SV);
    float* SA  = (float*)(g_scratch + O_SA);
    float* SB_ = (float*)(g_scratch + O_SB);
    float* COEF = (float*)(g_scratch + O_COEF);

    int gw = (blockIdx.x * blockDim.x + threadIdx.x) >> 5;
    int lane = threadIdx.x & 31;
    if (gw >= Mm * Hh) return;
    int m = gw / Hh;
    int h = gw % Hh;
    int b = m >> 10;
    int t = m & (Tt - 1);
    int n = lane * 2;
    int c = h * Nn + n;
    size_t gbase = (size_t)m * Cc + c;

    float2 k2   = *(const float2*)(Kf + gbase);
    float2 kkwv = *(const float2*)(kkw + c);
    float kkx = k2.x * kkwv.x, kky = k2.y * kkwv.y;
    float ss = kkx * kkx + kky * kky;
#pragma unroll
    for (int o = 16; o; o >>= 1) ss += __shfl_xor_sync(0xffffffffu, ss, o);
    float inv = 1.f / fmaxf(sqrtf(ss), 1e-12f);

    float2 ar2 = *(const float2*)(ARAW + gbase);
    float2 a0v = *(const float2*)(a0 + c);
    float ax = sigmoidf_(a0v.x + ar2.x);
    float ay = sigmoidf_(a0v.y + ar2.y);

    float2 kav = *(const float2*)(kaw + c);
    float khx = k2.x * (1.f + (ax - 1.f) * kav.x);
    float khy = k2.y * (1.f + (ay - 1.f) * kav.y);

    float2 wr2 = *(const float2*)(WRAW + gbase);
    float2 w0v = *(const float2*)(w0 + c);
    float wx = EXP_NEG_HALF * sigmoidf_(w0v.x + wr2.x);
    float wy = EXP_NEG_HALF * sigmoidf_(w0v.y + wr2.y);

    float2 vr2 = *(const float2*)(VRAW + gbase);
    float2 v0v = *(const float2*)(v0 + c);
    float svx = sigmoidf_(v0v.x + vr2.x);
    float svy = sigmoidf_(v0v.y + vr2.y);
    float2 vv  = *(const float2*)(Vf + gbase);
    float2 vf2 = *(const float2*)(vfirst + gbase);
    float vhx = vv.x + (vf2.x - vv.x) * svx;
    float vhy = vv.y + (vf2.y - vv.y) * svy;

    float2 r2  = *(const float2*)(Rf + gbase);
    float2 rkv = *(const float2*)(rkw + c);
    float cf = r2.x * khx * rkv.x + r2.y * khy * rkv.y;
#pragma unroll
    for (int o = 16; o; o >>= 1) cf += __shfl_xor_sync(0xffffffffu, cf, o);

    int bh = b * Hh + h;
    size_t sbase = ((size_t)bh * Tt + t) * Nn + n;
    *(float2*)(SR + sbase)  = r2;
    *(float2*)(SW + sbase)  = make_float2(wx, wy);
    *(float2*)(SK + sbase)  = make_float2(khx, khy);
    *(float2*)(SV + sbase)  = make_float2(vhx, vhy);
    *(float2*)(SA + sbase)  = make_float2(-kkx * inv, -kky * inv);
    *(float2*)(SB_ + sbase) = make_float2(kkx * inv * ax, kky * inv * ay);
    if (lane == 0) COEF[(size_t)bh * Tt + t] = cf;
}

// ---------------- sequential scan over T (smem cp.async pipeline) ----------------
__global__ void __launch_bounds__(64) k_scan() {
    __shared__ __align__(16) float sbuf[SCAN_D][6 * 64];

    const float* gptr[6];
    gptr[0] = (const float*)(g_scratch + O_SW);
    gptr[1] = (const float*)(g_scratch + O_SA);
    gptr[2] = (const float*)(g_scratch + O_SB);
    gptr[3] = (const float*)(g_scratch + O_SK);
    gptr[4] = (const float*)(g_scratch + O_SR);
    gptr[5] = (const float*)(g_scratch + O_SV);
    float* WKV = (float*)(g_scratch + O_WKV);

    int blk = blockIdx.x;
    int bh = blk >> 3;
    int q = blk & 7;
    int tid = threadIdx.x;
    int rowl = tid >> 3;
    int cg = tid & 7;
    int row = q * 8 + rowl;
    size_t base = (size_t)bh * Tt * Nn;
    int co = cg * 8;

    auto issue_stage = [&](int t) {
        int slot = t & (SCAN_D - 1);
#pragma unroll
        for (int c = tid; c < 96; c += 64) {
            int a = c >> 4;
            int off = (c & 15) * 4;
            cp_async16(&sbuf[slot][a * 64 + off],
                       gptr[a] + base + (size_t)t * Nn + off);
        }
    };

#pragma unroll
    for (int s = 0; s < SCAN_D - 1; s++) {
        issue_stage(s);
        CP_COMMIT();
    }

    float st[8];
#pragma unroll
    for (int j = 0; j < 8; j++) st[j] = 0.f;

    for (int t = 0; t < Tt; t++) {
        __syncthreads();
        int tp = t + SCAN_D - 1;
        if (tp < Tt) issue_stage(tp);
        CP_COMMIT();
        CP_WAIT7();
        __syncthreads();

        const float* S = sbuf[t & (SCAN_D - 1)];
        float4 wv0 = *(const float4*)(S + 0 * 64 + co);
        float4 wv1 = *(const float4*)(S + 0 * 64 + co + 4);
        float4 av0 = *(const float4*)(S + 1 * 64 + co);
        float4 av1 = *(const float4*)(S + 1 * 64 + co + 4);
        float4 bv0 = *(const float4*)(S + 2 * 64 + co);
        float4 bv1 = *(const float4*)(S + 2 * 64 + co + 4);
        float4 kv0 = *(const float4*)(S + 3 * 64 + co);
        float4 kv1 = *(const float4*)(S + 3 * 64 + co + 4);
        float4 rv0 = *(const float4*)(S + 4 * 64 + co);
        float4 rv1 = *(const float4*)(S + 4 * 64 + co + 4);
        float cv = S[5 * 64 + row];

        float sa = 0.f;
#pragma unroll
        for (int j = 0; j < 8; j++)
            sa = fmaf(st[j], getc(j < 4 ? av0 : av1, j & 3), sa);
        sa += __shfl_xor_sync(0xffffffffu, sa, 1);
        sa += __shfl_xor_sync(0xffffffffu, sa, 2);
        sa += __shfl_xor_sync(0xffffffffu, sa, 4);

        float outp = 0.f;
#pragma unroll
        for (int j = 0; j < 8; j++) {
            float wj = getc(j < 4 ? wv0 : wv1, j & 3);
            float bj = getc(j < 4 ? bv0 : bv1, j & 3);
            float kj = getc(j < 4 ? kv0 : kv1, j & 3);
            float rj = getc(j < 4 ? rv0 : rv1, j & 3);
            float s = fmaf(st[j], wj, fmaf(sa, bj, cv * kj));
            st[j] = s;
            outp = fmaf(s, rj, outp);
        }
        outp += __shfl_xor_sync(0xffffffffu, outp, 1);
        outp += __shfl_xor_sync(0xffffffffu, outp, 2);
        outp += __shfl_xor_sync(0xffffffffu, outp, 4);
        if (cg == 0) WKV[base + (size_t)t * Nn + row] = outp;
    }
}

// ---------------- groupnorm + bonus + gate ----------------
__global__ void k_gn(const float* __restrict__ lng, const float* __restrict__ lnb) {
    const float* WKV  = (const float*)(g_scratch + O_WKV);
    const float* SV   = (const float*)(g_scratch + O_SV);
    const float* COEF = (const float*)(g_scratch + O_COEF);
    const float* GG   = (const float*)(g_scratch + O_GG);
    __half* XO = (__half*)(g_scratch + O_XO);

    int gw = (blockIdx.x * blockDim.x + threadIdx.x) >> 5;
    int lane = threadIdx.x & 31;
    if (gw >= Mm * Hh) return;
    int m = gw / Hh;
    int h = gw % Hh;
    int b = m >> 10;
    int t = m & (Tt - 1);
    int bh = b * Hh + h;
    int n = lane * 2;
    int c = h * Nn + n;
    size_t sbase = ((size_t)bh * Tt + t) * Nn + n;

    float2 x2 = *(const float2*)(WKV + sbase);
    float s1 = x2.x + x2.y;
    float s2 = x2.x * x2.x + x2.y * x2.y;
#pragma unroll
    for (int o = 16; o; o >>= 1) {
        s1 += __shfl_xor_sync(0xffffffffu, s1, o);
        s2 += __shfl_xor_sync(0xffffffffu, s2, o);
    }
    float mu = s1 * (1.f / 64.f);
    float var = s2 * (1.f / 64.f) - mu * mu;
    float inv = rsqrtf(fmaxf(var, 0.f) + LN_EPS_F);

    float2 g2v = *(const float2*)(lng + c);
    float2 b2v = *(const float2*)(lnb + c);
    float xn0 = (x2.x - mu) * inv * g2v.x + b2v.x;
    float xn1 = (x2.y - mu) * inv * g2v.y + b2v.y;

    float cf = COEF[(size_t)bh * Tt + t];
    float2 vh2 = *(const float2*)(SV + sbase);
    float xo0 = xn0 + cf * vh2.x;
    float xo1 = xn1 + cf * vh2.y;

    float2 gg2 = *(const float2*)(GG + (size_t)m * Cc + c);
    *(__half2*)(XO + (size_t)m * Cc + c) = __floats2half2_rn(xo0 * gg2.x, xo1 * gg2.y);
}

// ---------------- host launcher ----------------
static inline int cdiv_(int a, int b) { return (a + b - 1) / b; }

extern "C" void kernel_launch(void* const* d_in, const int* in_sizes, int n_in,
                              void* d_out, int out_size) {
    (void)in_sizes; (void)n_in; (void)out_size;
    const float* x       = (const float*)d_in[0];
    const float* v_first = (const float*)d_in[1];
    const float* x_r  = (const float*)d_in[2];
    const float* x_w  = (const float*)d_in[3];
    const float* x_k  = (const float*)d_in[4];
    const float* x_v  = (const float*)d_in[5];
    const float* x_a  = (const float*)d_in[6];
    const float* x_g  = (const float*)d_in[7];
    const float* w0   = (const float*)d_in[8];
    const float* w1   = (const float*)d_in[9];
    const float* a0   = (const float*)d_in[11];
    const float* a1   = (const float*)d_in[12];
    const float* v0   = (const float*)d_in[14];
    const float* v1   = (const float*)d_in[15];
    const float* g1   = (const float*)d_in[17];
    const float* k_k  = (const float*)d_in[19];
    const float* k_a  = (const float*)d_in[20];
    const float* r_k  = (const float*)d_in[21];
    const float* ln_g = (const float*)d_in[26];
    const float* ln_b = (const float*)d_in[27];

    cudaFuncSetAttribute(k2_gemm_rkv,  cudaFuncAttributeMaxDynamicSharedMemorySize, K2_SMEM);
    cudaFuncSetAttribute(k2_gemm_down, cudaFuncAttributeMaxDynamicSharedMemorySize, K2_SMEM);
    cudaFuncSetAttribute(k2_gemm_out,  cudaFuncAttributeMaxDynamicSharedMemorySize, K2_SMEM);
    cudaFuncSetAttribute(k2_gemm_up,   cudaFuncAttributeMaxDynamicSharedMemorySize, UP_SMEM);

    {
        dim3 g(cdiv_(Cc * Cc / 4, 256), 12);
        k_convert_all<<<g, 256>>>((const float*)d_in[22], (const float*)d_in[23],
                                  (const float*)d_in[24], (const float*)d_in[25],
                                  w1, a1, v1, g1,
                                  (const float*)d_in[10], (const float*)d_in[13],
                                  (const float*)d_in[16], (const float*)d_in[18]);
    }

    k_mix<<<cdiv_(Mm * (Cc / 4), 256), 256>>>(x, x_r, x_w, x_k, x_v, x_a, x_g);

    {
        dim3 g(cdiv_(Cc, FBN), Mm / FBM, 3);
        k2_gemm_rkv<<<g, 256, K2_SMEM>>>();
    }
    {
        dim3 g(1, Mm / FBM, 4);
        k2_gemm_up<<<g, 256, UP_SMEM>>>();
    }
    {
        dim3 g(cdiv_(Cc, FBN), Mm / FBM, 4);
        k2_gemm_down<<<g, 256, K2_SMEM>>>();
    }

    k_prepare<<<Mm * Hh / 8, 256>>>(v_first, w0, a0, v0, k_k, k_a, r_k);

    k_scan<<<Bb * Hh * (Nn / 8), 64>>>();

    k_gn<<<Mm * Hh / 8, 256>>>(ln_g, ln_b);

    {
        dim3 g(cdiv_(Cc, FBN), Mm / FBM);
        k2_gemm_out<<<g, 256, K2_SMEM>>>((float*)d_out);
    }
}

// round 8
// speedup vs baseline: 1.5819x; 1.0071x over previous
#include <cuda_runtime.h>
#include <cuda_fp16.h>
#include <mma.h>
#include <cstdint>

using namespace nvcuda;

// ---------------- problem constants ----------------
namespace {
constexpr int Bb = 4, Tt = 1024, Cc = 960, Hh = 15, Nn = 64;
constexpr int Mm = Bb * Tt;                    // 4096 tokens
constexpr float LN_EPS_F = 0.00064f;
constexpr float EXP_NEG_HALF = 0.6065306597126334f;

constexpr size_t MC  = (size_t)Mm * Cc;
constexpr size_t SZ_H_MC = MC * 2;
constexpr size_t SZ_F_MC = MC * 4;

constexpr size_t O_XR   = 0;
constexpr size_t O_XW   = O_XR + SZ_H_MC;
constexpr size_t O_XK   = O_XW + SZ_H_MC;
constexpr size_t O_XV   = O_XK + SZ_H_MC;
constexpr size_t O_XA   = O_XV + SZ_H_MC;
constexpr size_t O_XG   = O_XA + SZ_H_MC;
constexpr size_t O_WR16 = O_XG + SZ_H_MC;
constexpr size_t O_WK16 = O_WR16 + (size_t)Cc * Cc * 2;
constexpr size_t O_WV16 = O_WK16 + (size_t)Cc * Cc * 2;
constexpr size_t O_WO16 = O_WV16 + (size_t)Cc * Cc * 2;
constexpr size_t O_W116 = O_WO16 + (size_t)Cc * Cc * 2;
constexpr size_t O_A116 = O_W116 + (size_t)Cc * 64 * 2;
constexpr size_t O_V116 = O_A116 + (size_t)Cc * 64 * 2;
constexpr size_t O_G116 = O_V116 + (size_t)Cc * 32 * 2;
constexpr size_t O_W216 = O_G116 + (size_t)Cc * 128 * 2;
constexpr size_t O_A216 = O_W216 + (size_t)64 * Cc * 2;
constexpr size_t O_V216 = O_A216 + (size_t)64 * Cc * 2;
constexpr size_t O_G216 = O_V216 + (size_t)32 * Cc * 2;
constexpr size_t O_HW   = O_G216 + (size_t)128 * Cc * 2;
constexpr size_t O_HA   = O_HW + (size_t)Mm * 64 * 2;
constexpr size_t O_HV   = O_HA + (size_t)Mm * 64 * 2;
constexpr size_t O_HG   = O_HV + (size_t)Mm * 32 * 2;
constexpr size_t O_R    = O_HG + (size_t)Mm * 128 * 2;
constexpr size_t O_K    = O_R + SZ_F_MC;
constexpr size_t O_V    = O_K + SZ_F_MC;
constexpr size_t O_WRAW = O_V + SZ_F_MC;
constexpr size_t O_ARAW = O_WRAW + SZ_F_MC;
constexpr size_t O_VRAW = O_ARAW + SZ_F_MC;
constexpr size_t O_GG   = O_VRAW + SZ_F_MC;
// interleaved scan input: [bh][t][6][64] fp32  (6*64*4 = 1536 B per token)
constexpr size_t O_SS   = O_GG + SZ_F_MC;
constexpr size_t SZ_SS  = (size_t)Bb * Hh * Tt * 6 * 64 * 4;
constexpr size_t O_COEF = O_SS + SZ_SS;
constexpr size_t O_WKV  = O_COEF + (size_t)Bb * Hh * Tt * 4;
constexpr size_t O_XO   = O_WKV + SZ_F_MC;
constexpr size_t SCRATCH_TOTAL = O_XO + SZ_H_MC;

// fast GEMM config (128x128 CTA tile, 8 warps 2Mx4N, 64x32 warp tile)
constexpr int FBM = 128, FBN = 128, FBK = 32;
constexpr int FLDA = 40, FLDB = 136;
constexpr int NSTG = 3;
constexpr int STAGE_A = FBM * FLDA;            // halves
constexpr int STAGE_B = FBK * FLDB;            // halves
constexpr int K2_SMEM = NSTG * (STAGE_A + STAGE_B) * 2;     // 56832 B
constexpr int UPLDC = 132;
constexpr int UP_SMEM = (FBM * UPLDC * 4) > K2_SMEM ? (FBM * UPLDC * 4) : K2_SMEM;

// scan pipeline depth
constexpr int SCAN_D = 8;
} // namespace

__device__ __align__(256) unsigned char g_scratch[SCRATCH_TOTAL];

// ---------------- helpers ----------------
__device__ __forceinline__ float sigmoidf_(float x) { return 1.f / (1.f + expf(-x)); }
__device__ __forceinline__ float getc(const float4& v, int j) {
    return j == 0 ? v.x : j == 1 ? v.y : j == 2 ? v.z : v.w;
}
__device__ __forceinline__ void cp_async16(void* smem_dst, const void* gsrc) {
    unsigned int d = (unsigned int)__cvta_generic_to_shared(smem_dst);
    asm volatile("cp.async.cg.shared.global [%0], [%1], 16;" :: "r"(d), "l"(gsrc));
}
__device__ __forceinline__ void cp_async16p(void* smem_dst, const void* gsrc, bool pred) {
    unsigned int d = (unsigned int)__cvta_generic_to_shared(smem_dst);
    int b = pred ? 16 : 0;
    asm volatile("cp.async.cg.shared.global [%0], [%1], 16, %2;" :: "r"(d), "l"(gsrc), "r"(b));
}
#define CP_COMMIT() asm volatile("cp.async.commit_group;")
#define CP_WAIT2()  asm volatile("cp.async.wait_group 2;")
#define CP_WAIT7()  asm volatile("cp.async.wait_group 7;")

// ---------------- fused weight convert ----------------
__global__ void k_convert_all(const float* p0, const float* p1, const float* p2,
                              const float* p3, const float* p4, const float* p5,
                              const float* p6, const float* p7, const float* p8,
                              const float* p9, const float* p10, const float* p11) {
    const int sizes[12] = {Cc * Cc, Cc * Cc, Cc * Cc, Cc * Cc,
                           Cc * 64, Cc * 64, Cc * 32, Cc * 128,
                           64 * Cc, 64 * Cc, 32 * Cc, 128 * Cc};
    const size_t doff[12] = {O_WR16, O_WK16, O_WV16, O_WO16,
                             O_W116, O_A116, O_V116, O_G116,
                             O_W216, O_A216, O_V216, O_G216};
    const float* srcs[12] = {p0, p1, p2, p3, p4, p5, p6, p7, p8, p9, p10, p11};
    int z = blockIdx.y;
    int n = sizes[z];
    int i = (blockIdx.x * 256 + threadIdx.x) * 4;
    if (i >= n) return;
    const float* s = srcs[z];
    __half* d = (__half*)(g_scratch + doff[z]);
    float4 v = *(const float4*)(s + i);
    *(__half2*)(d + i)     = __floats2half2_rn(v.x, v.y);
    *(__half2*)(d + i + 2) = __floats2half2_rn(v.z, v.w);
}

// ---------------- token shift + mix ----------------
__global__ void k_mix(const float* __restrict__ x,
                      const float* __restrict__ mr, const float* __restrict__ mw,
                      const float* __restrict__ mk, const float* __restrict__ mv,
                      const float* __restrict__ ma, const float* __restrict__ mg) {
    int i = blockIdx.x * blockDim.x + threadIdx.x;
    if (i >= Mm * (Cc / 4)) return;
    int m = i / (Cc / 4);
    int c = (i % (Cc / 4)) * 4;
    int t = m & (Tt - 1);
    float4 xc = *(const float4*)(x + (size_t)m * Cc + c);
    float4 xp = make_float4(0.f, 0.f, 0.f, 0.f);
    if (t > 0) xp = *(const float4*)(x + (size_t)(m - 1) * Cc + c);
    float4 dx = make_float4(xp.x - xc.x, xp.y - xc.y, xp.z - xc.z, xp.w - xc.w);

    const float* mixes[6] = {mr, mw, mk, mv, ma, mg};
    const size_t offs[6] = {O_XR, O_XW, O_XK, O_XV, O_XA, O_XG};
#pragma unroll
    for (int q = 0; q < 6; q++) {
        float4 mmv = *(const float4*)(mixes[q] + c);
        __half* out = (__half*)(g_scratch + offs[q]);
        __half2 h0 = __floats2half2_rn(xc.x + dx.x * mmv.x, xc.y + dx.y * mmv.y);
        __half2 h1 = __floats2half2_rn(xc.z + dx.z * mmv.z, xc.w + dx.w * mmv.w);
        *(__half2*)(out + (size_t)m * Cc + c)     = h0;
        *(__half2*)(out + (size_t)m * Cc + c + 2) = h1;
    }
}

// ---------------- fast GEMM compute core: 3-stage cp.async, 64x32 warp tile ----------------
__device__ __forceinline__ void gemm_core(const __half* __restrict__ A,
                                          const __half* __restrict__ Bm,
                                          int Nd, int Kd, int bm, int bn,
                                          __half* sA, __half* sB,
                                          wmma::fragment<wmma::accumulator, 16, 16, 16, float> (&acc)[4][2]) {
    int tid = threadIdx.x;
    int warp = tid >> 5;
    int wr = warp >> 2;
    int wc = warp & 3;
    int KT = Kd / FBK;

    auto load_stage = [&](int kt, int s) {
        const __half* Ag = A + (size_t)bm * Kd + kt * FBK;
        __half* sAs = sA + s * STAGE_A;
        __half* sBs = sB + s * STAGE_B;
#pragma unroll
        for (int u = 0; u < 2; u++) {
            int id = tid + u * 256;
            int r = id >> 2;
            int c = (id & 3) * 8;
            cp_async16(sAs + r * FLDA + c, Ag + (size_t)r * Kd + c);
        }
#pragma unroll
        for (int u = 0; u < 2; u++) {
            int id = tid + u * 256;
            int r = id >> 4;
            int c = (id & 15) * 8;
            bool p = (bn + c) < Nd;
            const __half* Bg = Bm + (size_t)(kt * FBK + r) * Nd + bn + c;
            cp_async16p(sBs + r * FLDB + c, p ? Bg : (const __half*)Bm, p);
        }
    };

#pragma unroll
    for (int i = 0; i < 4; i++)
#pragma unroll
        for (int j = 0; j < 2; j++) wmma::fill_fragment(acc[i][j], 0.f);

    load_stage(0, 0);
    CP_COMMIT();
    if (KT > 1) load_stage(1, 1);
    CP_COMMIT();

    for (int kt = 0; kt < KT; kt++) {
        if (kt + 2 < KT) load_stage(kt + 2, (kt + 2) % NSTG);
        CP_COMMIT();
        CP_WAIT2();
        __syncthreads();
        const __half* sAs = sA + (kt % NSTG) * STAGE_A;
        const __half* sBs = sB + (kt % NSTG) * STAGE_B;
#pragma unroll
        for (int ks = 0; ks < 2; ks++) {
            wmma::fragment<wmma::matrix_b, 16, 16, 16, __half, wmma::row_major> fb[2];
            wmma::load_matrix_sync(fb[0], sBs + (ks * 16) * FLDB + wc * 32, FLDB);
            wmma::load_matrix_sync(fb[1], sBs + (ks * 16) * FLDB + wc * 32 + 16, FLDB);
#pragma unroll
            for (int i = 0; i < 4; i++) {
                wmma::fragment<wmma::matrix_a, 16, 16, 16, __half, wmma::row_major> fa;
                wmma::load_matrix_sync(fa, sAs + (wr * 64 + i * 16) * FLDA + ks * 16, FLDA);
                wmma::mma_sync(acc[i][0], fa, fb[0], acc[i][0]);
                wmma::mma_sync(acc[i][1], fa, fb[1], acc[i][1]);
            }
        }
        __syncthreads();
    }
}

// fp32 direct-store wrapper
__device__ __forceinline__ void gemm_fast_f32(const __half* A, const __half* Bm,
                                              float* Cf, int Nd, int Kd,
                                              int bm, int bn, __half* sA, __half* sB) {
    wmma::fragment<wmma::accumulator, 16, 16, 16, float> acc[4][2];
    gemm_core(A, Bm, Nd, Kd, bm, bn, sA, sB, acc);
    int warp = threadIdx.x >> 5;
    int wr = warp >> 2;
    int wc = warp & 3;
#pragma unroll
    for (int i = 0; i < 4; i++)
#pragma unroll
        for (int j = 0; j < 2; j++) {
            int gc = bn + wc * 32 + j * 16;
            if (gc < Nd)
                wmma::store_matrix_sync(Cf + (size_t)(bm + wr * 64 + i * 16) * Nd + gc,
                                        acc[i][j], Nd, wmma::mem_row_major);
        }
}

__global__ void __launch_bounds__(256, 2) k2_gemm_rkv() {
    extern __shared__ __align__(16) unsigned char dyn[];
    __half* sA = (__half*)dyn;
    __half* sB = sA + NSTG * STAGE_A;
    int z = blockIdx.z;
    const size_t aoff[3] = {O_XR, O_XK, O_XV};
    const size_t boff[3] = {O_WR16, O_WK16, O_WV16};
    const size_t coff[3] = {O_R, O_K, O_V};
    gemm_fast_f32((const __half*)(g_scratch + aoff[z]), (const __half*)(g_scratch + boff[z]),
                  (float*)(g_scratch + coff[z]), Cc, Cc,
                  blockIdx.y * FBM, blockIdx.x * FBN, sA, sB);
}

__global__ void __launch_bounds__(256, 2) k2_gemm_down() {
    extern __shared__ __align__(16) unsigned char dyn[];
    __half* sA = (__half*)dyn;
    __half* sB = sA + NSTG * STAGE_A;
    int z = blockIdx.z;
    const size_t aoff[4] = {O_HW, O_HA, O_HV, O_HG};
    const size_t boff[4] = {O_W216, O_A216, O_V216, O_G216};
    const size_t coff[4] = {O_WRAW, O_ARAW, O_VRAW, O_GG};
    const int kd[4] = {64, 64, 32, 128};
    gemm_fast_f32((const __half*)(g_scratch + aoff[z]), (const __half*)(g_scratch + boff[z]),
                  (float*)(g_scratch + coff[z]), Cc, kd[z],
                  blockIdx.y * FBM, blockIdx.x * FBN, sA, sB);
}

__global__ void __launch_bounds__(256, 2) k2_gemm_out(float* __restrict__ out) {
    extern __shared__ __align__(16) unsigned char dyn[];
    __half* sA = (__half*)dyn;
    __half* sB = sA + NSTG * STAGE_A;
    gemm_fast_f32((const __half*)(g_scratch + O_XO), (const __half*)(g_scratch + O_WO16),
                  out, Cc, Cc, blockIdx.y * FBM, blockIdx.x * FBN, sA, sB);
}

// lora-up: fp16 + activation epilogue via smem staging
__global__ void __launch_bounds__(256, 2) k2_gemm_up() {
    extern __shared__ __align__(16) unsigned char dyn[];
    __half* sA = (__half*)dyn;
    __half* sB = sA + NSTG * STAGE_A;
    float*  sC = (float*)dyn;

    int z = blockIdx.z;
    const size_t aoff[4] = {O_XW, O_XA, O_XV, O_XG};
    const size_t boff[4] = {O_W116, O_A116, O_V116, O_G116};
    const size_t coff[4] = {O_HW, O_HA, O_HV, O_HG};
    const int ndA[4] = {64, 64, 32, 128};
    const int epA[4] = {1, 3, 3, 2};
    int Nd = ndA[z];
    int epi = epA[z];
    int bm = blockIdx.y * FBM;

    wmma::fragment<wmma::accumulator, 16, 16, 16, float> acc[4][2];
    gemm_core((const __half*)(g_scratch + aoff[z]), (const __half*)(g_scratch + boff[z]),
              Nd, Cc, bm, 0, sA, sB, acc);

    int tid = threadIdx.x;
    int warp = tid >> 5;
    int wr = warp >> 2;
    int wc = warp & 3;
#pragma unroll
    for (int i = 0; i < 4; i++)
#pragma unroll
        for (int j = 0; j < 2; j++)
            wmma::store_matrix_sync(sC + (wr * 64 + i * 16) * UPLDC + wc * 32 + j * 16,
                                    acc[i][j], UPLDC, wmma::mem_row_major);
    __syncthreads();

    __half* Cout = (__half*)(g_scratch + coff[z]);
    for (int idx = tid; idx < FBM * 128; idx += 256) {
        int r = idx >> 7;
        int c = idx & 127;
        if (c >= Nd) continue;
        float v = sC[r * UPLDC + c];
        if (epi == 1)      v = tanhf(v);
        else if (epi == 2) v = sigmoidf_(v);
        Cout[(size_t)(bm + r) * Nd + c] = __float2half(v);
    }
}

// ---------------- per-token prepare (writes interleaved [6][64] blocks) ----------------
__global__ void k_prepare(const float* __restrict__ vfirst,
                          const float* __restrict__ w0, const float* __restrict__ a0,
                          const float* __restrict__ v0, const float* __restrict__ kkw,
                          const float* __restrict__ kaw, const float* __restrict__ rkw) {
    const float* Rf   = (const float*)(g_scratch + O_R);
    const float* Kf   = (const float*)(g_scratch + O_K);
    const float* Vf   = (const float*)(g_scratch + O_V);
    const float* WRAW = (const float*)(g_scratch + O_WRAW);
    const float* ARAW = (const float*)(g_scratch + O_ARAW);
    const float* VRAW = (const float*)(g_scratch + O_VRAW);
    float* SS   = (float*)(g_scratch + O_SS);
    float* COEF = (float*)(g_scratch + O_COEF);

    int gw = (blockIdx.x * blockDim.x + threadIdx.x) >> 5;
    int lane = threadIdx.x & 31;
    if (gw >= Mm * Hh) return;
    int m = gw / Hh;
    int h = gw % Hh;
    int b = m >> 10;
    int t = m & (Tt - 1);
    int n = lane * 2;
    int c = h * Nn + n;
    size_t gbase = (size_t)m * Cc + c;

    float2 k2   = *(const float2*)(Kf + gbase);
    float2 kkwv = *(const float2*)(kkw + c);
    float kkx = k2.x * kkwv.x, kky = k2.y * kkwv.y;
    float ss = kkx * kkx + kky * kky;
#pragma unroll
    for (int o = 16; o; o >>= 1) ss += __shfl_xor_sync(0xffffffffu, ss, o);
    float inv = 1.f / fmaxf(sqrtf(ss), 1e-12f);

    float2 ar2 = *(const float2*)(ARAW + gbase);
    float2 a0v = *(const float2*)(a0 + c);
    float ax = sigmoidf_(a0v.x + ar2.x);
    float ay = sigmoidf_(a0v.y + ar2.y);

    float2 kav = *(const float2*)(kaw + c);
    float khx = k2.x * (1.f + (ax - 1.f) * kav.x);
    float khy = k2.y * (1.f + (ay - 1.f) * kav.y);

    float2 wr2 = *(const float2*)(WRAW + gbase);
    float2 w0v = *(const float2*)(w0 + c);
    float wx = EXP_NEG_HALF * sigmoidf_(w0v.x + wr2.x);
    float wy = EXP_NEG_HALF * sigmoidf_(w0v.y + wr2.y);

    float2 vr2 = *(const float2*)(VRAW + gbase);
    float2 v0v = *(const float2*)(v0 + c);
    float svx = sigmoidf_(v0v.x + vr2.x);
    float svy = sigmoidf_(v0v.y + vr2.y);
    float2 vv  = *(const float2*)(Vf + gbase);
    float2 vf2 = *(const float2*)(vfirst + gbase);
    float vhx = vv.x + (vf2.x - vv.x) * svx;
    float vhy = vv.y + (vf2.y - vv.y) * svy;

    float2 r2  = *(const float2*)(Rf + gbase);
    float2 rkv = *(const float2*)(rkw + c);
    float cf = r2.x * khx * rkv.x + r2.y * khy * rkv.y;
#pragma unroll
    for (int o = 16; o; o >>= 1) cf += __shfl_xor_sync(0xffffffffu, cf, o);

    int bh = b * Hh + h;
    // interleaved token block: [bh*Tt + t][a][64], a: 0=W 1=A 2=B 3=K 4=R 5=V
    float* tok = SS + ((size_t)bh * Tt + t) * 384 + n;
    *(float2*)(tok + 0 * 64) = make_float2(wx, wy);
    *(float2*)(tok + 1 * 64) = make_float2(-kkx * inv, -kky * inv);
    *(float2*)(tok + 2 * 64) = make_float2(kkx * inv * ax, kky * inv * ay);
    *(float2*)(tok + 3 * 64) = make_float2(khx, khy);
    *(float2*)(tok + 4 * 64) = r2;
    *(float2*)(tok + 5 * 64) = make_float2(vhx, vhy);
    if (lane == 0) COEF[(size_t)bh * Tt + t] = cf;
}

// ---------------- sequential scan over T (smem cp.async pipeline, contiguous stage reads) --
__global__ void __launch_bounds__(64) k_scan() {
    __shared__ __align__(16) float sbuf[SCAN_D][6 * 64];

    const float* SS = (const float*)(g_scratch + O_SS);
    float* WKV = (float*)(g_scratch + O_WKV);

    int blk = blockIdx.x;
    int bh = blk >> 3;
    int q = blk & 7;
    int tid = threadIdx.x;
    int rowl = tid >> 3;
    int cg = tid & 7;
    int row = q * 8 + rowl;
    size_t base = (size_t)bh * Tt * Nn;          // for WKV output
    size_t base_ss = (size_t)bh * Tt * 384;      // interleaved input
    int co = cg * 8;

    auto issue_stage = [&](int t) {
        int slot = t & (SCAN_D - 1);
        const float* src = SS + base_ss + (size_t)t * 384;
        // 96 chunks of 16B (1536 B contiguous); 64 threads
#pragma unroll
        for (int c = tid; c < 96; c += 64)
            cp_async16(&sbuf[slot][c * 4], src + c * 4);
    };

#pragma unroll
    for (int s = 0; s < SCAN_D - 1; s++) {
        issue_stage(s);
        CP_COMMIT();
    }

    float st[8];
#pragma unroll
    for (int j = 0; j < 8; j++) st[j] = 0.f;

    for (int t = 0; t < Tt; t++) {
        __syncthreads();
        int tp = t + SCAN_D - 1;
        if (tp < Tt) issue_stage(tp);
        CP_COMMIT();
        CP_WAIT7();
        __syncthreads();

        const float* S = sbuf[t & (SCAN_D - 1)];
        float4 wv0 = *(const float4*)(S + 0 * 64 + co);
        float4 wv1 = *(const float4*)(S + 0 * 64 + co + 4);
        float4 av0 = *(const float4*)(S + 1 * 64 + co);
        float4 av1 = *(const float4*)(S + 1 * 64 + co + 4);
        float4 bv0 = *(const float4*)(S + 2 * 64 + co);
        float4 bv1 = *(const float4*)(S + 2 * 64 + co + 4);
        float4 kv0 = *(const float4*)(S + 3 * 64 + co);
        float4 kv1 = *(const float4*)(S + 3 * 64 + co + 4);
        float4 rv0 = *(const float4*)(S + 4 * 64 + co);
        float4 rv1 = *(const float4*)(S + 4 * 64 + co + 4);
        float cv = S[5 * 64 + row];

        float sa = 0.f;
#pragma unroll
        for (int j = 0; j < 8; j++)
            sa = fmaf(st[j], getc(j < 4 ? av0 : av1, j & 3), sa);
        sa += __shfl_xor_sync(0xffffffffu, sa, 1);
        sa += __shfl_xor_sync(0xffffffffu, sa, 2);
        sa += __shfl_xor_sync(0xffffffffu, sa, 4);

        float outp = 0.f;
#pragma unroll
        for (int j = 0; j < 8; j++) {
            float wj = getc(j < 4 ? wv0 : wv1, j & 3);
            float bj = getc(j < 4 ? bv0 : bv1, j & 3);
            float kj = getc(j < 4 ? kv0 : kv1, j & 3);
            float rj = getc(j < 4 ? rv0 : rv1, j & 3);
            float s = fmaf(st[j], wj, fmaf(sa, bj, cv * kj));
            st[j] = s;
            outp = fmaf(s, rj, outp);
        }
        outp += __shfl_xor_sync(0xffffffffu, outp, 1);
        outp += __shfl_xor_sync(0xffffffffu, outp, 2);
        outp += __shfl_xor_sync(0xffffffffu, outp, 4);
        if (cg == 0) WKV[base + (size_t)t * Nn + row] = outp;
    }
}

// ---------------- groupnorm + bonus + gate ----------------
__global__ void k_gn(const float* __restrict__ lng, const float* __restrict__ lnb) {
    const float* WKV  = (const float*)(g_scratch + O_WKV);
    const float* SS   = (const float*)(g_scratch + O_SS);
    const float* COEF = (const float*)(g_scratch + O_COEF);
    const float* GG   = (const float*)(g_scratch + O_GG);
    __half* XO = (__half*)(g_scratch + O_XO);

    int gw = (blockIdx.x * blockDim.x + threadIdx.x) >> 5;
    int lane = threadIdx.x & 31;
    if (gw >= Mm * Hh) return;
    int m = gw / Hh;
    int h = gw % Hh;
    int b = m >> 10;
    int t = m & (Tt - 1);
    int bh = b * Hh + h;
    int n = lane * 2;
    int c = h * Nn + n;
    size_t tok = (size_t)bh * Tt + t;
    size_t sbase = tok * Nn + n;

    float2 x2 = *(const float2*)(WKV + sbase);
    float s1 = x2.x + x2.y;
    float s2 = x2.x * x2.x + x2.y * x2.y;
#pragma unroll
    for (int o = 16; o; o >>= 1) {
        s1 += __shfl_xor_sync(0xffffffffu, s1, o);
        s2 += __shfl_xor_sync(0xffffffffu, s2, o);
    }
    float mu = s1 * (1.f / 64.f);
    float var = s2 * (1.f / 64.f) - mu * mu;
    float inv = rsqrtf(fmaxf(var, 0.f) + LN_EPS_F);

    float2 g2v = *(const float2*)(lng + c);
    float2 b2v = *(const float2*)(lnb + c);
    float xn0 = (x2.x - mu) * inv * g2v.x + b2v.x;
    float xn1 = (x2.y - mu) * inv * g2v.y + b2v.y;

    float cf = COEF[tok];
    float2 vh2 = *(const float2*)(SS + tok * 384 + 5 * 64 + n);
    float xo0 = xn0 + cf * vh2.x;
    float xo1 = xn1 + cf * vh2.y;

    float2 gg2 = *(const float2*)(GG + (size_t)m * Cc + c);
    *(__half2*)(XO + (size_t)m * Cc + c) = __floats2half2_rn(xo0 * gg2.x, xo1 * gg2.y);
}

// ---------------- host launcher ----------------
static inline int cdiv_(int a, int b) { return (a + b - 1) / b; }

extern "C" void kernel_launch(void* const* d_in, const int* in_sizes, int n_in,
                              void* d_out, int out_size) {
    (void)in_sizes; (void)n_in; (void)out_size;
    const float* x       = (const float*)d_in[0];
    const float* v_first = (const float*)d_in[1];
    const float* x_r  = (const float*)d_in[2];
    const float* x_w  = (const float*)d_in[3];
    const float* x_k  = (const float*)d_in[4];
    const float* x_v  = (const float*)d_in[5];
    const float* x_a  = (const float*)d_in[6];
    const float* x_g  = (const float*)d_in[7];
    const float* w0   = (const float*)d_in[8];
    const float* w1   = (const float*)d_in[9];
    const float* a0   = (const float*)d_in[11];
    const float* a1   = (const float*)d_in[12];
    const float* v0   = (const float*)d_in[14];
    const float* v1   = (const float*)d_in[15];
    const float* g1   = (const float*)d_in[17];
    const float* k_k  = (const float*)d_in[19];
    const float* k_a  = (const float*)d_in[20];
    const float* r_k  = (const float*)d_in[21];
    const float* ln_g = (const float*)d_in[26];
    const float* ln_b = (const float*)d_in[27];

    // one-time setup (first call is the uncaptured correctness run)
    static cudaStream_t sA = nullptr, sB = nullptr;
    static cudaEvent_t e0 = nullptr, eA = nullptr, eB = nullptr, eA2 = nullptr, eB2 = nullptr;
    if (!sA) {
        cudaStreamCreateWithFlags(&sA, cudaStreamNonBlocking);
        cudaStreamCreateWithFlags(&sB, cudaStreamNonBlocking);
        cudaEventCreateWithFlags(&e0,  cudaEventDisableTiming);
        cudaEventCreateWithFlags(&eA,  cudaEventDisableTiming);
        cudaEventCreateWithFlags(&eB,  cudaEventDisableTiming);
        cudaEventCreateWithFlags(&eA2, cudaEventDisableTiming);
        cudaEventCreateWithFlags(&eB2, cudaEventDisableTiming);
        cudaFuncSetAttribute(k2_gemm_rkv,  cudaFuncAttributeMaxDynamicSharedMemorySize, K2_SMEM);
        cudaFuncSetAttribute(k2_gemm_down, cudaFuncAttributeMaxDynamicSharedMemorySize, K2_SMEM);
        cudaFuncSetAttribute(k2_gemm_out,  cudaFuncAttributeMaxDynamicSharedMemorySize, K2_SMEM);
        cudaFuncSetAttribute(k2_gemm_up,   cudaFuncAttributeMaxDynamicSharedMemorySize, UP_SMEM);
    }

    // fork from capture-origin (default) stream
    cudaEventRecord(e0, 0);
    cudaStreamWaitEvent(sA, e0, 0);
    cudaStreamWaitEvent(sB, e0, 0);

    // phase 1: convert (sA)  ||  mix (sB)
    {
        dim3 g(cdiv_(Cc * Cc / 4, 256), 12);
        k_convert_all<<<g, 256, 0, sA>>>((const float*)d_in[22], (const float*)d_in[23],
                                         (const float*)d_in[24], (const float*)d_in[25],
                                         w1, a1, v1, g1,
                                         (const float*)d_in[10], (const float*)d_in[13],
                                         (const float*)d_in[16], (const float*)d_in[18]);
    }
    k_mix<<<cdiv_(Mm * (Cc / 4), 256), 256, 0, sB>>>(x, x_r, x_w, x_k, x_v, x_a, x_g);

    // join both phases (rkv and up each need convert+mix)
    cudaEventRecord(eA, sA);
    cudaEventRecord(eB, sB);
    cudaStreamWaitEvent(sA, eB, 0);
    cudaStreamWaitEvent(sB, eA, 0);

    // phase 2: rkv (sA)  ||  up -> down (sB)
    {
        dim3 g(cdiv_(Cc, FBN), Mm / FBM, 3);
        k2_gemm_rkv<<<g, 256, K2_SMEM, sA>>>();
    }
    {
        dim3 g(1, Mm / FBM, 4);
        k2_gemm_up<<<g, 256, UP_SMEM, sB>>>();
    }
    {
        dim3 g(cdiv_(Cc, FBN), Mm / FBM, 4);
        k2_gemm_down<<<g, 256, K2_SMEM, sB>>>();
    }

    // join back into default stream
    cudaEventRecord(eA2, sA);
    cudaEventRecord(eB2, sB);
    cudaStreamWaitEvent(0, eA2, 0);
    cudaStreamWaitEvent(0, eB2, 0);

    k_prepare<<<Mm * Hh / 8, 256>>>(v_first, w0, a0, v0, k_k, k_a, r_k);

    k_scan<<<Bb * Hh * (Nn / 8), 64>>>();

    k_gn<<<Mm * Hh / 8, 256>>>(ln_g, ln_b);

    {
        dim3 g(cdiv_(Cc, FBN), Mm / FBM);
        k2_gemm_out<<<g, 256, K2_SMEM>>>((float*)d_out);
    }
}